// round 2
// baseline (speedup 1.0000x reference)
#include <cuda_runtime.h>

#define Dn 1024
#define Bn 16
#define Rn 100

// Scratch (device globals; no allocations allowed)
__device__ float g_Wsum[Dn * Dn];   // mean_r gate_W[r,k,j]  (k-major, j contig)
__device__ float g_mb[Dn];          // mean_r gate_b[r,k]
__device__ float g_Ccos[Dn * Dn];   // cos(phase)[i,m]
__device__ float g_ET[Dn * Dn];     // E^T  [j,n]
__device__ float g_M[Dn * Dn];      // M = QW @ E     [m,j]
__device__ float g_G[Dn * Dn];      // G = M @ Wsum^T [m,k]
__device__ float g_GT[Dn * Dn];     // G^T            [k,m]

// ---------------------------------------------------------------------------
// Reduction of gate_W over R: Wsum[k,j] = (1/R) sum_r gate_W[r,k,j]
// Streams 400MB; fully coalesced (all threads scan the same r-slab together).
// ---------------------------------------------------------------------------
__global__ void reduce_w_kernel(const float* __restrict__ gw) {
    int i4 = blockIdx.x * blockDim.x + threadIdx.x;   // 0 .. D*D/4-1
    const float4* p = reinterpret_cast<const float4*>(gw);
    float ax = 0.f, ay = 0.f, az = 0.f, aw = 0.f;
    #pragma unroll 4
    for (int r = 0; r < Rn; ++r) {
        float4 v = p[(size_t)r * (Dn * Dn / 4) + i4];
        ax += v.x; ay += v.y; az += v.z; aw += v.w;
    }
    const float inv = 1.0f / (float)Rn;
    float4 o; o.x = ax * inv; o.y = ay * inv; o.z = az * inv; o.w = aw * inv;
    reinterpret_cast<float4*>(g_Wsum)[i4] = o;
}

__global__ void reduce_b_kernel(const float* __restrict__ gb) {
    int k = blockIdx.x * blockDim.x + threadIdx.x;    // 0..1023
    float acc = 0.f;
    #pragma unroll 4
    for (int r = 0; r < Rn; ++r) acc += gb[r * Dn + k];
    g_mb[k] = acc / (float)Rn;
}

__global__ void cos_kernel(const float* __restrict__ ph) {
    int i = blockIdx.x * blockDim.x + threadIdx.x;
    g_Ccos[i] = cosf(ph[i]);
}

// ---------------------------------------------------------------------------
// 32x32 tiled transpose
// ---------------------------------------------------------------------------
__device__ __forceinline__ void transpose_body(const float* __restrict__ in,
                                               float* __restrict__ out) {
    __shared__ float tile[32][33];
    int x = blockIdx.x * 32 + threadIdx.x;
    int y = blockIdx.y * 32 + threadIdx.y;
    #pragma unroll
    for (int j = 0; j < 32; j += 8)
        tile[threadIdx.y + j][threadIdx.x] = in[(y + j) * Dn + x];
    __syncthreads();
    x = blockIdx.y * 32 + threadIdx.x;
    y = blockIdx.x * 32 + threadIdx.y;
    #pragma unroll
    for (int j = 0; j < 32; j += 8)
        out[(y + j) * Dn + x] = tile[threadIdx.x][threadIdx.y + j];
}

__global__ void transpose_E_kernel(const float* __restrict__ E) { transpose_body(E, g_ET); }
__global__ void transpose_G_kernel()                             { transpose_body(g_G, g_GT); }

// ---------------------------------------------------------------------------
// Dot-form GEMM: C[i,n] = sum_k A[i,k] * B[n,k]   (both operands k-contiguous)
// ---------------------------------------------------------------------------
template <int BM, int BN, int BK, int TM, int TN>
__device__ __forceinline__ void gemm_dot_body(const float* __restrict__ A,
                                              const float* __restrict__ B,
                                              float* __restrict__ C) {
    constexpr int THREADS = (BM / TM) * (BN / TN);
    constexpr int PADM = BM + 4;
    constexpr int PADN = BN + 4;
    constexpr int KV4 = BK / 4;
    constexpr int LOADS_A = (BM * BK / 4) / THREADS;
    constexpr int LOADS_B = (BN * BK / 4) / THREADS;

    __shared__ float As[BK][PADM];
    __shared__ float Bs[BK][PADN];

    const int i0 = blockIdx.y * BM;
    const int n0 = blockIdx.x * BN;
    const int tid = threadIdx.x;
    const int tr = tid / (BN / TN);
    const int tc = tid % (BN / TN);

    float acc[TM][TN];
    #pragma unroll
    for (int a = 0; a < TM; ++a)
        #pragma unroll
        for (int b = 0; b < TN; ++b) acc[a][b] = 0.f;

    for (int k0 = 0; k0 < Dn; k0 += BK) {
        #pragma unroll
        for (int l = 0; l < LOADS_A; ++l) {
            int idx = tid + l * THREADS;
            int row = idx / KV4, c4 = idx % KV4;
            float4 v = *reinterpret_cast<const float4*>(A + (size_t)(i0 + row) * Dn + k0 + c4 * 4);
            As[c4 * 4 + 0][row] = v.x; As[c4 * 4 + 1][row] = v.y;
            As[c4 * 4 + 2][row] = v.z; As[c4 * 4 + 3][row] = v.w;
        }
        #pragma unroll
        for (int l = 0; l < LOADS_B; ++l) {
            int idx = tid + l * THREADS;
            int row = idx / KV4, c4 = idx % KV4;
            float4 v = *reinterpret_cast<const float4*>(B + (size_t)(n0 + row) * Dn + k0 + c4 * 4);
            Bs[c4 * 4 + 0][row] = v.x; Bs[c4 * 4 + 1][row] = v.y;
            Bs[c4 * 4 + 2][row] = v.z; Bs[c4 * 4 + 3][row] = v.w;
        }
        __syncthreads();

        #pragma unroll
        for (int kk = 0; kk < BK; ++kk) {
            float ar[TM], br[TN];
            #pragma unroll
            for (int t = 0; t < TM / 4; ++t) {
                float4 v = *reinterpret_cast<const float4*>(&As[kk][tr * TM + t * 4]);
                ar[t * 4 + 0] = v.x; ar[t * 4 + 1] = v.y; ar[t * 4 + 2] = v.z; ar[t * 4 + 3] = v.w;
            }
            #pragma unroll
            for (int t = 0; t < TN / 4; ++t) {
                float4 v = *reinterpret_cast<const float4*>(&Bs[kk][tc * TN + t * 4]);
                br[t * 4 + 0] = v.x; br[t * 4 + 1] = v.y; br[t * 4 + 2] = v.z; br[t * 4 + 3] = v.w;
            }
            #pragma unroll
            for (int a = 0; a < TM; ++a)
                #pragma unroll
                for (int b = 0; b < TN; ++b) acc[a][b] += ar[a] * br[b];
        }
        __syncthreads();
    }

    #pragma unroll
    for (int a = 0; a < TM; ++a) {
        int row = i0 + tr * TM + a;
        #pragma unroll
        for (int b = 0; b < TN; b += 4) {
            float4 v; v.x = acc[a][b]; v.y = acc[a][b + 1]; v.z = acc[a][b + 2]; v.w = acc[a][b + 3];
            *reinterpret_cast<float4*>(C + (size_t)row * Dn + n0 + tc * TN + b) = v;
        }
    }
}

// M[m,j] = sum_n QW[m,n] * ET[j,n]
__global__ void gemm_M_kernel(const float* __restrict__ qw) {
    gemm_dot_body<64, 64, 16, 4, 4>(qw, g_ET, g_M);
}
// G[m,k] = sum_j M[m,j] * Wsum[k,j]
__global__ void gemm_G_kernel() {
    gemm_dot_body<64, 64, 16, 4, 4>(g_M, g_Wsum, g_G);
}

// ---------------------------------------------------------------------------
// Final GEMM: out[b,i,k] = sum_m (Ccos[i,m] * x[b,m]) * GT[k,m] + mb[k]
// blockIdx = (k_tile, i_tile, b); 128x128 tile, 8x8 per thread, BK=16.
// ---------------------------------------------------------------------------
__global__ void gemm_final_kernel(const float* __restrict__ x,
                                  float* __restrict__ out) {
    constexpr int BM = 128, BN = 128, BK = 16, TM = 8, TN = 8;
    constexpr int THREADS = 256;
    constexpr int PAD = BM + 4;
    constexpr int KV4 = BK / 4;

    __shared__ float As[BK][PAD];
    __shared__ float Bs[BK][PAD];

    const int b  = blockIdx.z;
    const int i0 = blockIdx.y * BM;
    const int n0 = blockIdx.x * BN;   // k (output column) tile
    const float* __restrict__ xb = x + (size_t)b * Dn;

    const int tid = threadIdx.x;
    const int tr = tid / (BN / TN);
    const int tc = tid % (BN / TN);

    float acc[TM][TN];
    #pragma unroll
    for (int a = 0; a < TM; ++a)
        #pragma unroll
        for (int c = 0; c < TN; ++c) acc[a][c] = 0.f;

    for (int k0 = 0; k0 < Dn; k0 += BK) {
        #pragma unroll
        for (int l = 0; l < 2; ++l) {
            int idx = tid + l * THREADS;
            int row = idx / KV4, c4 = idx % KV4;
            float4 v  = *reinterpret_cast<const float4*>(g_Ccos + (size_t)(i0 + row) * Dn + k0 + c4 * 4);
            float4 xs = *reinterpret_cast<const float4*>(xb + k0 + c4 * 4);
            As[c4 * 4 + 0][row] = v.x * xs.x; As[c4 * 4 + 1][row] = v.y * xs.y;
            As[c4 * 4 + 2][row] = v.z * xs.z; As[c4 * 4 + 3][row] = v.w * xs.w;
        }
        #pragma unroll
        for (int l = 0; l < 2; ++l) {
            int idx = tid + l * THREADS;
            int row = idx / KV4, c4 = idx % KV4;
            float4 v = *reinterpret_cast<const float4*>(g_GT + (size_t)(n0 + row) * Dn + k0 + c4 * 4);
            Bs[c4 * 4 + 0][row] = v.x; Bs[c4 * 4 + 1][row] = v.y;
            Bs[c4 * 4 + 2][row] = v.z; Bs[c4 * 4 + 3][row] = v.w;
        }
        __syncthreads();

        #pragma unroll
        for (int kk = 0; kk < BK; ++kk) {
            float ar[TM], br[TN];
            #pragma unroll
            for (int t = 0; t < TM / 4; ++t) {
                float4 v = *reinterpret_cast<const float4*>(&As[kk][tr * TM + t * 4]);
                ar[t * 4 + 0] = v.x; ar[t * 4 + 1] = v.y; ar[t * 4 + 2] = v.z; ar[t * 4 + 3] = v.w;
            }
            #pragma unroll
            for (int t = 0; t < TN / 4; ++t) {
                float4 v = *reinterpret_cast<const float4*>(&Bs[kk][tc * TN + t * 4]);
                br[t * 4 + 0] = v.x; br[t * 4 + 1] = v.y; br[t * 4 + 2] = v.z; br[t * 4 + 3] = v.w;
            }
            #pragma unroll
            for (int a = 0; a < TM; ++a)
                #pragma unroll
                for (int c = 0; c < TN; ++c) acc[a][c] += ar[a] * br[c];
        }
        __syncthreads();
    }

    float* __restrict__ outb = out + (size_t)b * Dn * Dn;
    #pragma unroll
    for (int a = 0; a < TM; ++a) {
        int row = i0 + tr * TM + a;
        #pragma unroll
        for (int c = 0; c < TN; c += 4) {
            int col = n0 + tc * TN + c;
            float4 mbv = *reinterpret_cast<const float4*>(&g_mb[col]);
            float4 v;
            v.x = acc[a][c + 0] + mbv.x;
            v.y = acc[a][c + 1] + mbv.y;
            v.z = acc[a][c + 2] + mbv.z;
            v.w = acc[a][c + 3] + mbv.w;
            *reinterpret_cast<float4*>(outb + (size_t)row * Dn + col) = v;
        }
    }
}

// ---------------------------------------------------------------------------
// kernel_launch
// Inputs (metadata order): x(16,1,1024), quantum_weights(1024,1024),
// quantum_phase(1024,1024), entanglement_matrix(1024,1024),
// gate_W(100,1024,1024), gate_b(100,1024). Output: (16,1024,1024) fp32.
// ---------------------------------------------------------------------------
extern "C" void kernel_launch(void* const* d_in, const int* in_sizes, int n_in,
                              void* d_out, int out_size) {
    const float* x  = (const float*)d_in[0];
    const float* qw = (const float*)d_in[1];
    const float* ph = (const float*)d_in[2];
    const float* em = (const float*)d_in[3];
    const float* gw = (const float*)d_in[4];
    const float* gb = (const float*)d_in[5];
    float* out = (float*)d_out;

    // Independent precomputes
    reduce_w_kernel<<<(Dn * Dn / 4) / 256, 256>>>(gw);
    reduce_b_kernel<<<Dn / 256, 256>>>(gb);
    cos_kernel<<<(Dn * Dn) / 256, 256>>>(ph);
    transpose_E_kernel<<<dim3(Dn / 32, Dn / 32), dim3(32, 8)>>>(em);

    // M = QW @ E  (dot form against E^T)
    gemm_M_kernel<<<dim3(Dn / 64, Dn / 64), 256>>>(qw);
    // G = M @ Wsum^T
    gemm_G_kernel<<<dim3(Dn / 64, Dn / 64), 256>>>();
    // G^T for dot-form final GEMM
    transpose_G_kernel<<<dim3(Dn / 32, Dn / 32), dim3(32, 8)>>>();

    // out[b,i,k] = sum_m (cos(phase)[i,m]*x[b,m]) * GT[k,m] + mb[k]
    gemm_final_kernel<<<dim3(Dn / 128, Dn / 128, Bn), 256>>>(x, out);
}

// round 4
// speedup vs baseline: 1.5193x; 1.5193x over previous
#include <cuda_runtime.h>
#include <cuda_bf16.h>
#include <cstdint>

#define Dn 1024
#define Bn 16
#define Rn 100

// Scratch (device globals; no allocations allowed)
__device__ float g_Wsum[Dn * Dn];            // mean_r gate_W[r,k,j]
__device__ float g_mb[Dn];                   // mean_r gate_b[r,k]
__device__ float g_Ccos[Dn * Dn];            // cos(phase)[i,m]
__device__ float g_ET[Dn * Dn];              // E^T
__device__ float g_M[Dn * Dn];               // M = QW @ E
__device__ float g_G[Dn * Dn];               // G = M @ Wsum^T   [m,k]
__device__ __nv_bfloat16 g_GThi[Dn * Dn];    // bf16 hi of G^T   [k,m]
__device__ __nv_bfloat16 g_GTlo[Dn * Dn];    // bf16 lo of G^T   [k,m]

// ---------------------------------------------------------------------------
// Reduction of gate_W over R (HBM-bound, streams 400MB)
// ---------------------------------------------------------------------------
__global__ void reduce_w_kernel(const float* __restrict__ gw) {
    int i4 = blockIdx.x * blockDim.x + threadIdx.x;
    const float4* p = reinterpret_cast<const float4*>(gw);
    float ax = 0.f, ay = 0.f, az = 0.f, aw = 0.f;
    #pragma unroll 4
    for (int r = 0; r < Rn; ++r) {
        float4 v = p[(size_t)r * (Dn * Dn / 4) + i4];
        ax += v.x; ay += v.y; az += v.z; aw += v.w;
    }
    const float inv = 1.0f / (float)Rn;
    float4 o; o.x = ax * inv; o.y = ay * inv; o.z = az * inv; o.w = aw * inv;
    reinterpret_cast<float4*>(g_Wsum)[i4] = o;
}

__global__ void reduce_b_kernel(const float* __restrict__ gb) {
    int k = blockIdx.x * blockDim.x + threadIdx.x;
    float acc = 0.f;
    #pragma unroll 4
    for (int r = 0; r < Rn; ++r) acc += gb[r * Dn + k];
    g_mb[k] = acc / (float)Rn;
}

__global__ void cos_kernel(const float* __restrict__ ph) {
    int i = blockIdx.x * blockDim.x + threadIdx.x;
    g_Ccos[i] = cosf(ph[i]);
}

// ---------------------------------------------------------------------------
// Transposes
// ---------------------------------------------------------------------------
__global__ void transpose_E_kernel(const float* __restrict__ in) {
    __shared__ float tile[32][33];
    int x = blockIdx.x * 32 + threadIdx.x;
    int y = blockIdx.y * 32 + threadIdx.y;
    #pragma unroll
    for (int j = 0; j < 32; j += 8)
        tile[threadIdx.y + j][threadIdx.x] = in[(y + j) * Dn + x];
    __syncthreads();
    x = blockIdx.y * 32 + threadIdx.x;
    y = blockIdx.x * 32 + threadIdx.y;
    #pragma unroll
    for (int j = 0; j < 32; j += 8)
        g_ET[(y + j) * Dn + x] = tile[threadIdx.x][threadIdx.y + j];
}

// G[m,k] -> GT_hi/GT_lo[k,m] (bf16 split)
__global__ void split_GT_kernel() {
    __shared__ float tile[32][33];
    int x = blockIdx.x * 32 + threadIdx.x;   // k
    int y = blockIdx.y * 32 + threadIdx.y;   // m
    #pragma unroll
    for (int j = 0; j < 32; j += 8)
        tile[threadIdx.y + j][threadIdx.x] = g_G[(y + j) * Dn + x];
    __syncthreads();
    x = blockIdx.y * 32 + threadIdx.x;       // m
    y = blockIdx.x * 32 + threadIdx.y;       // k
    #pragma unroll
    for (int j = 0; j < 32; j += 8) {
        float v = tile[threadIdx.x][threadIdx.y + j];
        __nv_bfloat16 h = __float2bfloat16_rn(v);
        __nv_bfloat16 l = __float2bfloat16_rn(v - __bfloat162float(h));
        g_GThi[(y + j) * Dn + x] = h;
        g_GTlo[(y + j) * Dn + x] = l;
    }
}

// ---------------------------------------------------------------------------
// Small dot-form GEMM (proven Round-2 code): C[i,n] = sum_k A[i,k] * B[n,k]
// ---------------------------------------------------------------------------
template <int BM, int BN, int BK, int TM, int TN>
__device__ __forceinline__ void gemm_dot_body(const float* __restrict__ A,
                                              const float* __restrict__ B,
                                              float* __restrict__ C) {
    constexpr int THREADS = (BM / TM) * (BN / TN);
    constexpr int PADM = BM + 4;
    constexpr int PADN = BN + 4;
    constexpr int KV4 = BK / 4;
    constexpr int LOADS_A = (BM * BK / 4) / THREADS;
    constexpr int LOADS_B = (BN * BK / 4) / THREADS;

    __shared__ float As[BK][PADM];
    __shared__ float Bs[BK][PADN];

    const int i0 = blockIdx.y * BM;
    const int n0 = blockIdx.x * BN;
    const int tid = threadIdx.x;
    const int tr = tid / (BN / TN);
    const int tc = tid % (BN / TN);

    float acc[TM][TN];
    #pragma unroll
    for (int a = 0; a < TM; ++a)
        #pragma unroll
        for (int b = 0; b < TN; ++b) acc[a][b] = 0.f;

    for (int k0 = 0; k0 < Dn; k0 += BK) {
        #pragma unroll
        for (int l = 0; l < LOADS_A; ++l) {
            int idx = tid + l * THREADS;
            int row = idx / KV4, c4 = idx % KV4;
            float4 v = *reinterpret_cast<const float4*>(A + (size_t)(i0 + row) * Dn + k0 + c4 * 4);
            As[c4 * 4 + 0][row] = v.x; As[c4 * 4 + 1][row] = v.y;
            As[c4 * 4 + 2][row] = v.z; As[c4 * 4 + 3][row] = v.w;
        }
        #pragma unroll
        for (int l = 0; l < LOADS_B; ++l) {
            int idx = tid + l * THREADS;
            int row = idx / KV4, c4 = idx % KV4;
            float4 v = *reinterpret_cast<const float4*>(B + (size_t)(n0 + row) * Dn + k0 + c4 * 4);
            Bs[c4 * 4 + 0][row] = v.x; Bs[c4 * 4 + 1][row] = v.y;
            Bs[c4 * 4 + 2][row] = v.z; Bs[c4 * 4 + 3][row] = v.w;
        }
        __syncthreads();

        #pragma unroll
        for (int kk = 0; kk < BK; ++kk) {
            float ar[TM], br[TN];
            #pragma unroll
            for (int t = 0; t < TM / 4; ++t) {
                float4 v = *reinterpret_cast<const float4*>(&As[kk][tr * TM + t * 4]);
                ar[t * 4 + 0] = v.x; ar[t * 4 + 1] = v.y; ar[t * 4 + 2] = v.z; ar[t * 4 + 3] = v.w;
            }
            #pragma unroll
            for (int t = 0; t < TN / 4; ++t) {
                float4 v = *reinterpret_cast<const float4*>(&Bs[kk][tc * TN + t * 4]);
                br[t * 4 + 0] = v.x; br[t * 4 + 1] = v.y; br[t * 4 + 2] = v.z; br[t * 4 + 3] = v.w;
            }
            #pragma unroll
            for (int a = 0; a < TM; ++a)
                #pragma unroll
                for (int b = 0; b < TN; ++b) acc[a][b] += ar[a] * br[b];
        }
        __syncthreads();
    }

    #pragma unroll
    for (int a = 0; a < TM; ++a) {
        int row = i0 + tr * TM + a;
        #pragma unroll
        for (int b = 0; b < TN; b += 4) {
            float4 v; v.x = acc[a][b]; v.y = acc[a][b + 1]; v.z = acc[a][b + 2]; v.w = acc[a][b + 3];
            *reinterpret_cast<float4*>(C + (size_t)row * Dn + n0 + tc * TN + b) = v;
        }
    }
}

__global__ void gemm_M_kernel(const float* __restrict__ qw) {
    gemm_dot_body<64, 64, 16, 4, 4>(qw, g_ET, g_M);
}
__global__ void gemm_G_kernel() {
    gemm_dot_body<64, 64, 16, 4, 4>(g_M, g_Wsum, g_G);
}

// ---------------------------------------------------------------------------
// Final GEMM on tensor cores (mma.sync bf16, split-precision):
// out[b,i,k] = sum_m (Ccos[i,m]*x[b,m]) * GT[k,m] + mb[k]
// Block 128x128, BK=32, 8 warps (2m x 4n), warp tile 64x32.
// ---------------------------------------------------------------------------
__device__ __forceinline__ void mma_bf16(float* c, const uint32_t* a, const uint32_t* b) {
    asm volatile(
        "mma.sync.aligned.m16n8k16.row.col.f32.bf16.bf16.f32 "
        "{%0,%1,%2,%3}, {%4,%5,%6,%7}, {%8,%9}, {%0,%1,%2,%3};"
        : "+f"(c[0]), "+f"(c[1]), "+f"(c[2]), "+f"(c[3])
        : "r"(a[0]), "r"(a[1]), "r"(a[2]), "r"(a[3]), "r"(b[0]), "r"(b[1]));
}

__global__ void __launch_bounds__(256, 1)
gemm_final_kernel(const float* __restrict__ x, float* __restrict__ out) {
    constexpr int BM = 128, BN = 128, BK = 32;
    constexpr int PA = BK + 8;                 // 40 bf16 pitch = 80B (16B aligned)
    constexpr int MT = 4, NT = 4;              // 4x m16 subtiles, 4x n8 subtiles per warp

    __shared__ __nv_bfloat16 sAh[BM * PA];
    __shared__ __nv_bfloat16 sAl[BM * PA];
    __shared__ __nv_bfloat16 sBh[BN * PA];
    __shared__ __nv_bfloat16 sBl[BN * PA];

    const int b  = blockIdx.z;
    const int i0 = blockIdx.y * BM;
    const int n0 = blockIdx.x * BN;
    const float* __restrict__ xb = x + (size_t)b * Dn;

    const int tid  = threadIdx.x;
    const int w    = tid >> 5;
    const int lane = tid & 31;
    const int wm   = w >> 2;                   // 0..1
    const int wn   = w & 3;                    // 0..3
    const int gid  = lane >> 2;                // groupID 0..7
    const int tig  = lane & 3;                 // thread-in-group

    float acc[MT][NT][4];
    #pragma unroll
    for (int mt = 0; mt < MT; ++mt)
        #pragma unroll
        for (int nt = 0; nt < NT; ++nt)
            #pragma unroll
            for (int q = 0; q < 4; ++q) acc[mt][nt][q] = 0.f;

    for (int k0 = 0; k0 < Dn; k0 += BK) {
        // --- A tile: a = Ccos[i][m] * x[m], split to bf16 hi/lo ---
        // 128 rows x 32 cols = 1024 float4; 4 per thread
        #pragma unroll
        for (int l = 0; l < 4; ++l) {
            int idx = tid + l * 256;
            int row = idx >> 3, c4 = (idx & 7) * 4;
            float4 cv = *reinterpret_cast<const float4*>(g_Ccos + (size_t)(i0 + row) * Dn + k0 + c4);
            float4 xv = *reinterpret_cast<const float4*>(xb + k0 + c4);
            float vv[4] = {cv.x * xv.x, cv.y * xv.y, cv.z * xv.z, cv.w * xv.w};
            __nv_bfloat162 h01, h23, l01, l23;
            {
                __nv_bfloat16 h0 = __float2bfloat16_rn(vv[0]);
                __nv_bfloat16 h1 = __float2bfloat16_rn(vv[1]);
                __nv_bfloat16 h2 = __float2bfloat16_rn(vv[2]);
                __nv_bfloat16 h3 = __float2bfloat16_rn(vv[3]);
                h01 = __nv_bfloat162(h0, h1); h23 = __nv_bfloat162(h2, h3);
                l01 = __nv_bfloat162(__float2bfloat16_rn(vv[0] - __bfloat162float(h0)),
                                     __float2bfloat16_rn(vv[1] - __bfloat162float(h1)));
                l23 = __nv_bfloat162(__float2bfloat16_rn(vv[2] - __bfloat162float(h2)),
                                     __float2bfloat16_rn(vv[3] - __bfloat162float(h3)));
            }
            int off = row * PA + c4;
            *reinterpret_cast<__nv_bfloat162*>(&sAh[off])     = h01;
            *reinterpret_cast<__nv_bfloat162*>(&sAh[off + 2]) = h23;
            *reinterpret_cast<__nv_bfloat162*>(&sAl[off])     = l01;
            *reinterpret_cast<__nv_bfloat162*>(&sAl[off + 2]) = l23;
        }
        // --- B tile: GT hi/lo, 128 rows x 32 bf16 = 512 uint4; 2 each ---
        #pragma unroll
        for (int l = 0; l < 2; ++l) {
            int idx = tid + l * 256;
            int row = idx >> 2, c8 = (idx & 3) * 8;
            uint4 vh = *reinterpret_cast<const uint4*>(g_GThi + (size_t)(n0 + row) * Dn + k0 + c8);
            uint4 vl = *reinterpret_cast<const uint4*>(g_GTlo + (size_t)(n0 + row) * Dn + k0 + c8);
            *reinterpret_cast<uint4*>(&sBh[row * PA + c8]) = vh;
            *reinterpret_cast<uint4*>(&sBl[row * PA + c8]) = vl;
        }
        __syncthreads();

        #pragma unroll
        for (int ks = 0; ks < BK; ks += 16) {
            // B fragments for all 4 n-subtiles (hi & lo)
            uint32_t bh[NT][2], bl[NT][2];
            #pragma unroll
            for (int nt = 0; nt < NT; ++nt) {
                int bn = wn * 32 + nt * 8 + gid;
                int bk = ks + tig * 2;
                int o = bn * PA + bk;
                bh[nt][0] = *reinterpret_cast<const uint32_t*>(&sBh[o]);
                bh[nt][1] = *reinterpret_cast<const uint32_t*>(&sBh[o + 8]);
                bl[nt][0] = *reinterpret_cast<const uint32_t*>(&sBl[o]);
                bl[nt][1] = *reinterpret_cast<const uint32_t*>(&sBl[o + 8]);
            }
            #pragma unroll
            for (int mt = 0; mt < MT; ++mt) {
                int ar = wm * 64 + mt * 16 + gid;
                int ac = ks + tig * 2;
                int o0 = ar * PA + ac, o1 = (ar + 8) * PA + ac;
                uint32_t ah[4], al[4];
                ah[0] = *reinterpret_cast<const uint32_t*>(&sAh[o0]);
                ah[1] = *reinterpret_cast<const uint32_t*>(&sAh[o1]);
                ah[2] = *reinterpret_cast<const uint32_t*>(&sAh[o0 + 8]);
                ah[3] = *reinterpret_cast<const uint32_t*>(&sAh[o1 + 8]);
                al[0] = *reinterpret_cast<const uint32_t*>(&sAl[o0]);
                al[1] = *reinterpret_cast<const uint32_t*>(&sAl[o1]);
                al[2] = *reinterpret_cast<const uint32_t*>(&sAl[o0 + 8]);
                al[3] = *reinterpret_cast<const uint32_t*>(&sAl[o1 + 8]);
                #pragma unroll
                for (int nt = 0; nt < NT; ++nt) {
                    mma_bf16(acc[mt][nt], ah, bh[nt]);   // hi*hi
                    mma_bf16(acc[mt][nt], ah, bl[nt]);   // hi*lo
                    mma_bf16(acc[mt][nt], al, bh[nt]);   // lo*hi
                }
            }
        }
        __syncthreads();
    }

    // Epilogue: acc -> out, add mb[col]
    float* __restrict__ outb = out + (size_t)b * Dn * Dn;
    #pragma unroll
    for (int mt = 0; mt < MT; ++mt) {
        int row = i0 + wm * 64 + mt * 16 + gid;
        #pragma unroll
        for (int nt = 0; nt < NT; ++nt) {
            int col = n0 + wn * 32 + nt * 8 + tig * 2;
            float2 mbv = *reinterpret_cast<const float2*>(&g_mb[col]);
            float2 v0 = {acc[mt][nt][0] + mbv.x, acc[mt][nt][1] + mbv.y};
            float2 v1 = {acc[mt][nt][2] + mbv.x, acc[mt][nt][3] + mbv.y};
            *reinterpret_cast<float2*>(outb + (size_t)row * Dn + col) = v0;
            *reinterpret_cast<float2*>(outb + (size_t)(row + 8) * Dn + col) = v1;
        }
    }
}

// ---------------------------------------------------------------------------
// kernel_launch
// ---------------------------------------------------------------------------
extern "C" void kernel_launch(void* const* d_in, const int* in_sizes, int n_in,
                              void* d_out, int out_size) {
    const float* x  = (const float*)d_in[0];
    const float* qw = (const float*)d_in[1];
    const float* ph = (const float*)d_in[2];
    const float* em = (const float*)d_in[3];
    const float* gw = (const float*)d_in[4];
    const float* gb = (const float*)d_in[5];
    float* out = (float*)d_out;

    reduce_w_kernel<<<(Dn * Dn / 4) / 256, 256>>>(gw);
    reduce_b_kernel<<<Dn / 256, 256>>>(gb);
    cos_kernel<<<(Dn * Dn) / 256, 256>>>(ph);
    transpose_E_kernel<<<dim3(Dn / 32, Dn / 32), dim3(32, 8)>>>(em);

    gemm_M_kernel<<<dim3(Dn / 64, Dn / 64), 256>>>(qw);
    gemm_G_kernel<<<dim3(Dn / 64, Dn / 64), 256>>>();
    split_GT_kernel<<<dim3(Dn / 32, Dn / 32), dim3(32, 8)>>>();

    gemm_final_kernel<<<dim3(Dn / 128, Dn / 128, Bn), 256>>>(x, out);
}

// round 7
// speedup vs baseline: 1.6137x; 1.0621x over previous
#include <cuda_runtime.h>
#include <cuda_bf16.h>
#include <cstdint>

#define Dn 1024
#define Bn 16
#define Rn 100

typedef __nv_bfloat16 bf16;
typedef __nv_bfloat162 bf162;

// Scratch (device globals; no allocations allowed).
// NOTE: these are ONLY ever referenced from device code — passing them as
// kernel arguments from host code was the Round-6 bug (host shadow symbol).
__device__ float g_mb[Dn];              // mean_r gate_b
__device__ float g_Ccos[Dn * Dn];       // cos(phase)[i,m]
__device__ float g_G[Dn * Dn];          // G = M @ Wsum^T  [m,k] fp32
__device__ bf16 g_QWh[Dn * Dn], g_QWl[Dn * Dn];   // QW split      [m,n]
__device__ bf16 g_ETh[Dn * Dn], g_ETl[Dn * Dn];   // E^T split     [j,n]
__device__ bf16 g_Wh[Dn * Dn],  g_Wl[Dn * Dn];    // Wsum split    [k,j]
__device__ bf16 g_Mh[Dn * Dn],  g_Ml[Dn * Dn];    // M split       [m,j]
__device__ bf16 g_GTh[Dn * Dn], g_GTl[Dn * Dn];   // G^T split     [k,m]

__device__ __forceinline__ void split_f32(float v, bf16& h, bf16& l) {
    h = __float2bfloat16_rn(v);
    l = __float2bfloat16_rn(v - __bfloat162float(h));
}

// ---------------------------------------------------------------------------
// reduce gate_W over R -> Wsum bf16 hi/lo (HBM-bound, streams 400MB)
// ---------------------------------------------------------------------------
__global__ void reduce_w_kernel(const float* __restrict__ gw) {
    int i4 = blockIdx.x * blockDim.x + threadIdx.x;
    const float4* p = reinterpret_cast<const float4*>(gw);
    float ax = 0.f, ay = 0.f, az = 0.f, aw = 0.f;
    #pragma unroll 4
    for (int r = 0; r < Rn; ++r) {
        float4 v = p[(size_t)r * (Dn * Dn / 4) + i4];
        ax += v.x; ay += v.y; az += v.z; aw += v.w;
    }
    const float inv = 1.0f / (float)Rn;
    float vv[4] = {ax * inv, ay * inv, az * inv, aw * inv};
    bf16 h[4], l[4];
    #pragma unroll
    for (int q = 0; q < 4; ++q) split_f32(vv[q], h[q], l[q]);
    reinterpret_cast<bf162*>(g_Wh)[i4 * 2]     = bf162(h[0], h[1]);
    reinterpret_cast<bf162*>(g_Wh)[i4 * 2 + 1] = bf162(h[2], h[3]);
    reinterpret_cast<bf162*>(g_Wl)[i4 * 2]     = bf162(l[0], l[1]);
    reinterpret_cast<bf162*>(g_Wl)[i4 * 2 + 1] = bf162(l[2], l[3]);
}

__global__ void reduce_b_kernel(const float* __restrict__ gb) {
    int k = blockIdx.x * blockDim.x + threadIdx.x;
    float acc = 0.f;
    #pragma unroll 4
    for (int r = 0; r < Rn; ++r) acc += gb[r * Dn + k];
    g_mb[k] = acc / (float)Rn;
}

__global__ void cos_kernel(const float* __restrict__ ph) {
    int i = blockIdx.x * blockDim.x + threadIdx.x;
    g_Ccos[i] = cosf(ph[i]);
}

// QW fp32 -> bf16 hi/lo (elementwise)
__global__ void split_QW_kernel(const float* __restrict__ qw) {
    int i4 = blockIdx.x * blockDim.x + threadIdx.x;
    float4 v = reinterpret_cast<const float4*>(qw)[i4];
    float vv[4] = {v.x, v.y, v.z, v.w};
    bf16 h[4], l[4];
    #pragma unroll
    for (int q = 0; q < 4; ++q) split_f32(vv[q], h[q], l[q]);
    reinterpret_cast<bf162*>(g_QWh)[i4 * 2]     = bf162(h[0], h[1]);
    reinterpret_cast<bf162*>(g_QWh)[i4 * 2 + 1] = bf162(h[2], h[3]);
    reinterpret_cast<bf162*>(g_QWl)[i4 * 2]     = bf162(l[0], l[1]);
    reinterpret_cast<bf162*>(g_QWl)[i4 * 2 + 1] = bf162(l[2], l[3]);
}

// E [n,j] -> E^T split [j,n]
__global__ void transpose_split_E_kernel(const float* __restrict__ in) {
    __shared__ float tile[32][33];
    int x = blockIdx.x * 32 + threadIdx.x;
    int y = blockIdx.y * 32 + threadIdx.y;
    #pragma unroll
    for (int j = 0; j < 32; j += 8)
        tile[threadIdx.y + j][threadIdx.x] = in[(y + j) * Dn + x];
    __syncthreads();
    x = blockIdx.y * 32 + threadIdx.x;
    y = blockIdx.x * 32 + threadIdx.y;
    #pragma unroll
    for (int j = 0; j < 32; j += 8) {
        float v = tile[threadIdx.x][threadIdx.y + j];
        bf16 h, l; split_f32(v, h, l);
        g_ETh[(y + j) * Dn + x] = h;
        g_ETl[(y + j) * Dn + x] = l;
    }
}

// G [m,k] -> G^T split [k,m]
__global__ void split_GT_kernel() {
    __shared__ float tile[32][33];
    int x = blockIdx.x * 32 + threadIdx.x;
    int y = blockIdx.y * 32 + threadIdx.y;
    #pragma unroll
    for (int j = 0; j < 32; j += 8)
        tile[threadIdx.y + j][threadIdx.x] = g_G[(y + j) * Dn + x];
    __syncthreads();
    x = blockIdx.y * 32 + threadIdx.x;
    y = blockIdx.x * 32 + threadIdx.y;
    #pragma unroll
    for (int j = 0; j < 32; j += 8) {
        float v = tile[threadIdx.x][threadIdx.y + j];
        bf16 h, l; split_f32(v, h, l);
        g_GTh[(y + j) * Dn + x] = h;
        g_GTl[(y + j) * Dn + x] = l;
    }
}

// ---------------------------------------------------------------------------
// mma.sync bf16 m16n8k16 (row.col)
// ---------------------------------------------------------------------------
__device__ __forceinline__ void mma_bf16(float* c, const uint32_t* a, const uint32_t* b) {
    asm volatile(
        "mma.sync.aligned.m16n8k16.row.col.f32.bf16.bf16.f32 "
        "{%0,%1,%2,%3}, {%4,%5,%6,%7}, {%8,%9}, {%0,%1,%2,%3};"
        : "+f"(c[0]), "+f"(c[1]), "+f"(c[2]), "+f"(c[3])
        : "r"(a[0]), "r"(a[1]), "r"(a[2]), "r"(a[3]), "r"(b[0]), "r"(b[1]));
}

// ---------------------------------------------------------------------------
// Generic split GEMM body (dot-form): C[i,n] = sum_k A[i,k]*B[n,k]
// A,B given as bf16 hi/lo. 128x128 tile, BK=32, 8 warps (2m x 4n).
// Called from wrapper __global__ kernels that bind the device globals
// IN DEVICE CODE (host must never touch __device__ symbols).
// ---------------------------------------------------------------------------
template <int WRITE_BF16>
__device__ __forceinline__ void gemm_split_body(
        const bf16* __restrict__ Ah, const bf16* __restrict__ Al,
        const bf16* __restrict__ Bh, const bf16* __restrict__ Bl,
        float* __restrict__ Cf, bf16* __restrict__ Ch, bf16* __restrict__ Cl) {
    constexpr int BM = 128, BK = 32;
    constexpr int PA = BK + 8;   // 40 bf16 pitch
    constexpr int MT = 4, NT = 4;

    __shared__ bf16 sAh[BM * PA];
    __shared__ bf16 sAl[BM * PA];
    __shared__ bf16 sBh[BM * PA];
    __shared__ bf16 sBl[BM * PA];

    const int i0 = blockIdx.y * BM;
    const int n0 = blockIdx.x * BM;

    const int tid  = threadIdx.x;
    const int w    = tid >> 5;
    const int lane = tid & 31;
    const int wm   = w >> 2;
    const int wn   = w & 3;
    const int gid  = lane >> 2;
    const int tig  = lane & 3;

    float acc[MT][NT][4];
    #pragma unroll
    for (int mt = 0; mt < MT; ++mt)
        #pragma unroll
        for (int nt = 0; nt < NT; ++nt)
            #pragma unroll
            for (int q = 0; q < 4; ++q) acc[mt][nt][q] = 0.f;

    for (int k0 = 0; k0 < Dn; k0 += BK) {
        #pragma unroll
        for (int l = 0; l < 2; ++l) {
            int idx = tid + l * 256;
            int row = idx >> 2, c8 = (idx & 3) * 8;
            size_t goA = (size_t)(i0 + row) * Dn + k0 + c8;
            size_t goB = (size_t)(n0 + row) * Dn + k0 + c8;
            int so = row * PA + c8;
            *reinterpret_cast<uint4*>(&sAh[so]) = *reinterpret_cast<const uint4*>(Ah + goA);
            *reinterpret_cast<uint4*>(&sAl[so]) = *reinterpret_cast<const uint4*>(Al + goA);
            *reinterpret_cast<uint4*>(&sBh[so]) = *reinterpret_cast<const uint4*>(Bh + goB);
            *reinterpret_cast<uint4*>(&sBl[so]) = *reinterpret_cast<const uint4*>(Bl + goB);
        }
        __syncthreads();

        #pragma unroll
        for (int ks = 0; ks < BK; ks += 16) {
            uint32_t bh[NT][2], bl[NT][2];
            #pragma unroll
            for (int nt = 0; nt < NT; ++nt) {
                int bn = wn * 32 + nt * 8 + gid;
                int o = bn * PA + ks + tig * 2;
                bh[nt][0] = *reinterpret_cast<const uint32_t*>(&sBh[o]);
                bh[nt][1] = *reinterpret_cast<const uint32_t*>(&sBh[o + 8]);
                bl[nt][0] = *reinterpret_cast<const uint32_t*>(&sBl[o]);
                bl[nt][1] = *reinterpret_cast<const uint32_t*>(&sBl[o + 8]);
            }
            #pragma unroll
            for (int mt = 0; mt < MT; ++mt) {
                int ar = wm * 64 + mt * 16 + gid;
                int o0 = ar * PA + ks + tig * 2, o1 = o0 + 8 * PA;
                uint32_t ah[4], al[4];
                ah[0] = *reinterpret_cast<const uint32_t*>(&sAh[o0]);
                ah[1] = *reinterpret_cast<const uint32_t*>(&sAh[o1]);
                ah[2] = *reinterpret_cast<const uint32_t*>(&sAh[o0 + 8]);
                ah[3] = *reinterpret_cast<const uint32_t*>(&sAh[o1 + 8]);
                al[0] = *reinterpret_cast<const uint32_t*>(&sAl[o0]);
                al[1] = *reinterpret_cast<const uint32_t*>(&sAl[o1]);
                al[2] = *reinterpret_cast<const uint32_t*>(&sAl[o0 + 8]);
                al[3] = *reinterpret_cast<const uint32_t*>(&sAl[o1 + 8]);
                #pragma unroll
                for (int nt = 0; nt < NT; ++nt) {
                    mma_bf16(acc[mt][nt], ah, bh[nt]);
                    mma_bf16(acc[mt][nt], ah, bl[nt]);
                    mma_bf16(acc[mt][nt], al, bh[nt]);
                }
            }
        }
        __syncthreads();
    }

    #pragma unroll
    for (int mt = 0; mt < MT; ++mt) {
        int row = i0 + wm * 64 + mt * 16 + gid;
        #pragma unroll
        for (int nt = 0; nt < NT; ++nt) {
            int col = n0 + wn * 32 + nt * 8 + tig * 2;
            if (WRITE_BF16) {
                bf16 h0, l0, h1, l1;
                split_f32(acc[mt][nt][0], h0, l0);
                split_f32(acc[mt][nt][1], h1, l1);
                *reinterpret_cast<bf162*>(Ch + (size_t)row * Dn + col) = bf162(h0, h1);
                *reinterpret_cast<bf162*>(Cl + (size_t)row * Dn + col) = bf162(l0, l1);
                split_f32(acc[mt][nt][2], h0, l0);
                split_f32(acc[mt][nt][3], h1, l1);
                *reinterpret_cast<bf162*>(Ch + (size_t)(row + 8) * Dn + col) = bf162(h0, h1);
                *reinterpret_cast<bf162*>(Cl + (size_t)(row + 8) * Dn + col) = bf162(l0, l1);
            } else {
                float2 v0 = {acc[mt][nt][0], acc[mt][nt][1]};
                float2 v1 = {acc[mt][nt][2], acc[mt][nt][3]};
                *reinterpret_cast<float2*>(Cf + (size_t)row * Dn + col) = v0;
                *reinterpret_cast<float2*>(Cf + (size_t)(row + 8) * Dn + col) = v1;
            }
        }
    }
}

// Wrappers: bind device globals inside device code.
__global__ void __launch_bounds__(256, 1) gemm_M_kernel() {
    gemm_split_body<1>(g_QWh, g_QWl, g_ETh, g_ETl, nullptr, g_Mh, g_Ml);
}
__global__ void __launch_bounds__(256, 1) gemm_G_kernel() {
    gemm_split_body<0>(g_Mh, g_Ml, g_Wh, g_Wl, g_G, nullptr, nullptr);
}

// ---------------------------------------------------------------------------
// Final GEMM (proven Round-4 code):
// out[b,i,k] = sum_m (Ccos[i,m]*x[b,m]) * GT[k,m] + mb[k]
// ---------------------------------------------------------------------------
__global__ void __launch_bounds__(256, 1)
gemm_final_kernel(const float* __restrict__ x, float* __restrict__ out) {
    constexpr int BM = 128, BN = 128, BK = 32;
    constexpr int PA = BK + 8;
    constexpr int MT = 4, NT = 4;

    __shared__ bf16 sAh[BM * PA];
    __shared__ bf16 sAl[BM * PA];
    __shared__ bf16 sBh[BN * PA];
    __shared__ bf16 sBl[BN * PA];

    const int b  = blockIdx.z;
    const int i0 = blockIdx.y * BM;
    const int n0 = blockIdx.x * BN;
    const float* __restrict__ xb = x + (size_t)b * Dn;

    const int tid  = threadIdx.x;
    const int w    = tid >> 5;
    const int lane = tid & 31;
    const int wm   = w >> 2;
    const int wn   = w & 3;
    const int gid  = lane >> 2;
    const int tig  = lane & 3;

    float acc[MT][NT][4];
    #pragma unroll
    for (int mt = 0; mt < MT; ++mt)
        #pragma unroll
        for (int nt = 0; nt < NT; ++nt)
            #pragma unroll
            for (int q = 0; q < 4; ++q) acc[mt][nt][q] = 0.f;

    for (int k0 = 0; k0 < Dn; k0 += BK) {
        #pragma unroll
        for (int l = 0; l < 4; ++l) {
            int idx = tid + l * 256;
            int row = idx >> 3, c4 = (idx & 7) * 4;
            float4 cv = *reinterpret_cast<const float4*>(g_Ccos + (size_t)(i0 + row) * Dn + k0 + c4);
            float4 xv = *reinterpret_cast<const float4*>(xb + k0 + c4);
            float vv[4] = {cv.x * xv.x, cv.y * xv.y, cv.z * xv.z, cv.w * xv.w};
            bf16 h[4], l4[4];
            #pragma unroll
            for (int q = 0; q < 4; ++q) split_f32(vv[q], h[q], l4[q]);
            int off = row * PA + c4;
            *reinterpret_cast<bf162*>(&sAh[off])     = bf162(h[0], h[1]);
            *reinterpret_cast<bf162*>(&sAh[off + 2]) = bf162(h[2], h[3]);
            *reinterpret_cast<bf162*>(&sAl[off])     = bf162(l4[0], l4[1]);
            *reinterpret_cast<bf162*>(&sAl[off + 2]) = bf162(l4[2], l4[3]);
        }
        #pragma unroll
        for (int l = 0; l < 2; ++l) {
            int idx = tid + l * 256;
            int row = idx >> 2, c8 = (idx & 3) * 8;
            uint4 vh = *reinterpret_cast<const uint4*>(g_GTh + (size_t)(n0 + row) * Dn + k0 + c8);
            uint4 vl = *reinterpret_cast<const uint4*>(g_GTl + (size_t)(n0 + row) * Dn + k0 + c8);
            *reinterpret_cast<uint4*>(&sBh[row * PA + c8]) = vh;
            *reinterpret_cast<uint4*>(&sBl[row * PA + c8]) = vl;
        }
        __syncthreads();

        #pragma unroll
        for (int ks = 0; ks < BK; ks += 16) {
            uint32_t bh[NT][2], bl[NT][2];
            #pragma unroll
            for (int nt = 0; nt < NT; ++nt) {
                int bn = wn * 32 + nt * 8 + gid;
                int o = bn * PA + ks + tig * 2;
                bh[nt][0] = *reinterpret_cast<const uint32_t*>(&sBh[o]);
                bh[nt][1] = *reinterpret_cast<const uint32_t*>(&sBh[o + 8]);
                bl[nt][0] = *reinterpret_cast<const uint32_t*>(&sBl[o]);
                bl[nt][1] = *reinterpret_cast<const uint32_t*>(&sBl[o + 8]);
            }
            #pragma unroll
            for (int mt = 0; mt < MT; ++mt) {
                int ar = wm * 64 + mt * 16 + gid;
                int o0 = ar * PA + ks + tig * 2, o1 = o0 + 8 * PA;
                uint32_t ah[4], al[4];
                ah[0] = *reinterpret_cast<const uint32_t*>(&sAh[o0]);
                ah[1] = *reinterpret_cast<const uint32_t*>(&sAh[o1]);
                ah[2] = *reinterpret_cast<const uint32_t*>(&sAh[o0 + 8]);
                ah[3] = *reinterpret_cast<const uint32_t*>(&sAh[o1 + 8]);
                al[0] = *reinterpret_cast<const uint32_t*>(&sAl[o0]);
                al[1] = *reinterpret_cast<const uint32_t*>(&sAl[o1]);
                al[2] = *reinterpret_cast<const uint32_t*>(&sAl[o0 + 8]);
                al[3] = *reinterpret_cast<const uint32_t*>(&sAl[o1 + 8]);
                #pragma unroll
                for (int nt = 0; nt < NT; ++nt) {
                    mma_bf16(acc[mt][nt], ah, bh[nt]);
                    mma_bf16(acc[mt][nt], ah, bl[nt]);
                    mma_bf16(acc[mt][nt], al, bh[nt]);
                }
            }
        }
        __syncthreads();
    }

    float* __restrict__ outb = out + (size_t)b * Dn * Dn;
    #pragma unroll
    for (int mt = 0; mt < MT; ++mt) {
        int row = i0 + wm * 64 + mt * 16 + gid;
        #pragma unroll
        for (int nt = 0; nt < NT; ++nt) {
            int col = n0 + wn * 32 + nt * 8 + tig * 2;
            float2 mbv = *reinterpret_cast<const float2*>(&g_mb[col]);
            float2 v0 = {acc[mt][nt][0] + mbv.x, acc[mt][nt][1] + mbv.y};
            float2 v1 = {acc[mt][nt][2] + mbv.x, acc[mt][nt][3] + mbv.y};
            *reinterpret_cast<float2*>(outb + (size_t)row * Dn + col) = v0;
            *reinterpret_cast<float2*>(outb + (size_t)(row + 8) * Dn + col) = v1;
        }
    }
}

// ---------------------------------------------------------------------------
// kernel_launch — only harness pointers (d_in/d_out) cross the host/device line.
// ---------------------------------------------------------------------------
extern "C" void kernel_launch(void* const* d_in, const int* in_sizes, int n_in,
                              void* d_out, int out_size) {
    const float* x  = (const float*)d_in[0];
    const float* qw = (const float*)d_in[1];
    const float* ph = (const float*)d_in[2];
    const float* em = (const float*)d_in[3];
    const float* gw = (const float*)d_in[4];
    const float* gb = (const float*)d_in[5];
    float* out = (float*)d_out;

    reduce_w_kernel<<<(Dn * Dn / 4) / 256, 256>>>(gw);
    reduce_b_kernel<<<Dn / 256, 256>>>(gb);
    cos_kernel<<<(Dn * Dn) / 256, 256>>>(ph);
    split_QW_kernel<<<(Dn * Dn / 4) / 256, 256>>>(qw);
    transpose_split_E_kernel<<<dim3(Dn / 32, Dn / 32), dim3(32, 8)>>>(em);

    // M = QW @ E  (bf16-split tensor GEMM, bf16 hi/lo out)
    gemm_M_kernel<<<dim3(Dn / 128, Dn / 128), 256>>>();
    // G = M @ Wsum^T (fp32 out)
    gemm_G_kernel<<<dim3(Dn / 128, Dn / 128), 256>>>();
    split_GT_kernel<<<dim3(Dn / 32, Dn / 32), dim3(32, 8)>>>();

    gemm_final_kernel<<<dim3(Dn / 128, Dn / 128, Bn), 256>>>(x, out);
}

// round 8
// speedup vs baseline: 1.6752x; 1.0381x over previous
#include <cuda_runtime.h>
#include <cuda_bf16.h>
#include <cstdint>

#define Dn 1024
#define Bn 16
#define Rn 100

typedef __nv_bfloat16 bf16;
typedef __nv_bfloat162 bf162;

// Scratch (device globals; no allocations allowed).
// ONLY referenced from device code (Round-6 lesson: host must never touch these).
__device__ float g_mb[Dn];              // mean_r gate_b
__device__ float g_Ccos[Dn * Dn];       // cos(phase)[i,m]
__device__ float g_G[Dn * Dn];          // G = M @ Wsum^T  [m,k] fp32
__device__ bf16 g_QWh[Dn * Dn], g_QWl[Dn * Dn];   // QW split      [m,n]
__device__ bf16 g_ETh[Dn * Dn], g_ETl[Dn * Dn];   // E^T split     [j,n]
__device__ bf16 g_Wh[Dn * Dn],  g_Wl[Dn * Dn];    // Wsum split    [k,j]
__device__ bf16 g_Mh[Dn * Dn],  g_Ml[Dn * Dn];    // M split       [m,j]
__device__ bf16 g_GTh[Dn * Dn], g_GTl[Dn * Dn];   // G^T split     [k,m]
__device__ bf16 g_Ah[Bn * Dn * Dn];               // A=cos*x split hi [b,i,m]
__device__ bf16 g_Al[Bn * Dn * Dn];               // A=cos*x split lo

__device__ __forceinline__ void split_f32(float v, bf16& h, bf16& l) {
    h = __float2bfloat16_rn(v);
    l = __float2bfloat16_rn(v - __bfloat162float(h));
}

__device__ __forceinline__ void cp_async16(uint32_t dst_smem, const void* src) {
    asm volatile("cp.async.cg.shared.global [%0], [%1], 16;" :: "r"(dst_smem), "l"(src));
}
__device__ __forceinline__ void cp_commit() {
    asm volatile("cp.async.commit_group;");
}
__device__ __forceinline__ void cp_wait1() {
    asm volatile("cp.async.wait_group 1;");
}

// ---------------------------------------------------------------------------
// reduce gate_W over R -> Wsum bf16 hi/lo (HBM-bound, streams 400MB)
// ---------------------------------------------------------------------------
__global__ void reduce_w_kernel(const float* __restrict__ gw) {
    int i4 = blockIdx.x * blockDim.x + threadIdx.x;
    const float4* p = reinterpret_cast<const float4*>(gw);
    float ax = 0.f, ay = 0.f, az = 0.f, aw = 0.f;
    #pragma unroll 4
    for (int r = 0; r < Rn; ++r) {
        float4 v = p[(size_t)r * (Dn * Dn / 4) + i4];
        ax += v.x; ay += v.y; az += v.z; aw += v.w;
    }
    const float inv = 1.0f / (float)Rn;
    float vv[4] = {ax * inv, ay * inv, az * inv, aw * inv};
    bf16 h[4], l[4];
    #pragma unroll
    for (int q = 0; q < 4; ++q) split_f32(vv[q], h[q], l[q]);
    reinterpret_cast<bf162*>(g_Wh)[i4 * 2]     = bf162(h[0], h[1]);
    reinterpret_cast<bf162*>(g_Wh)[i4 * 2 + 1] = bf162(h[2], h[3]);
    reinterpret_cast<bf162*>(g_Wl)[i4 * 2]     = bf162(l[0], l[1]);
    reinterpret_cast<bf162*>(g_Wl)[i4 * 2 + 1] = bf162(l[2], l[3]);
}

__global__ void reduce_b_kernel(const float* __restrict__ gb) {
    int k = blockIdx.x * blockDim.x + threadIdx.x;
    float acc = 0.f;
    #pragma unroll 4
    for (int r = 0; r < Rn; ++r) acc += gb[r * Dn + k];
    g_mb[k] = acc / (float)Rn;
}

__global__ void cos_kernel(const float* __restrict__ ph) {
    int i = blockIdx.x * blockDim.x + threadIdx.x;
    g_Ccos[i] = cosf(ph[i]);
}

// QW fp32 -> bf16 hi/lo (elementwise)
__global__ void split_QW_kernel(const float* __restrict__ qw) {
    int i4 = blockIdx.x * blockDim.x + threadIdx.x;
    float4 v = reinterpret_cast<const float4*>(qw)[i4];
    float vv[4] = {v.x, v.y, v.z, v.w};
    bf16 h[4], l[4];
    #pragma unroll
    for (int q = 0; q < 4; ++q) split_f32(vv[q], h[q], l[q]);
    reinterpret_cast<bf162*>(g_QWh)[i4 * 2]     = bf162(h[0], h[1]);
    reinterpret_cast<bf162*>(g_QWh)[i4 * 2 + 1] = bf162(h[2], h[3]);
    reinterpret_cast<bf162*>(g_QWl)[i4 * 2]     = bf162(l[0], l[1]);
    reinterpret_cast<bf162*>(g_QWl)[i4 * 2 + 1] = bf162(l[2], l[3]);
}

// A[b,i,m] = Ccos[i,m] * x[b,m] -> bf16 hi/lo in global
__global__ void split_A_kernel(const float* __restrict__ x) {
    int b = blockIdx.y;
    int i4 = blockIdx.x * blockDim.x + threadIdx.x;   // 0..Dn*Dn/4-1
    float4 cv = reinterpret_cast<const float4*>(g_Ccos)[i4];
    int m = (i4 * 4) & (Dn - 1);
    float4 xv = *reinterpret_cast<const float4*>(x + (size_t)b * Dn + m);
    float vv[4] = {cv.x * xv.x, cv.y * xv.y, cv.z * xv.z, cv.w * xv.w};
    bf16 h[4], l[4];
    #pragma unroll
    for (int q = 0; q < 4; ++q) split_f32(vv[q], h[q], l[q]);
    size_t o2 = ((size_t)b << 19) + (size_t)i4 * 2;   // bf162 units
    reinterpret_cast<bf162*>(g_Ah)[o2]     = bf162(h[0], h[1]);
    reinterpret_cast<bf162*>(g_Ah)[o2 + 1] = bf162(h[2], h[3]);
    reinterpret_cast<bf162*>(g_Al)[o2]     = bf162(l[0], l[1]);
    reinterpret_cast<bf162*>(g_Al)[o2 + 1] = bf162(l[2], l[3]);
}

// E [n,j] -> E^T split [j,n]
__global__ void transpose_split_E_kernel(const float* __restrict__ in) {
    __shared__ float tile[32][33];
    int x = blockIdx.x * 32 + threadIdx.x;
    int y = blockIdx.y * 32 + threadIdx.y;
    #pragma unroll
    for (int j = 0; j < 32; j += 8)
        tile[threadIdx.y + j][threadIdx.x] = in[(y + j) * Dn + x];
    __syncthreads();
    x = blockIdx.y * 32 + threadIdx.x;
    y = blockIdx.x * 32 + threadIdx.y;
    #pragma unroll
    for (int j = 0; j < 32; j += 8) {
        float v = tile[threadIdx.x][threadIdx.y + j];
        bf16 h, l; split_f32(v, h, l);
        g_ETh[(y + j) * Dn + x] = h;
        g_ETl[(y + j) * Dn + x] = l;
    }
}

// G [m,k] -> G^T split [k,m]
__global__ void split_GT_kernel() {
    __shared__ float tile[32][33];
    int x = blockIdx.x * 32 + threadIdx.x;
    int y = blockIdx.y * 32 + threadIdx.y;
    #pragma unroll
    for (int j = 0; j < 32; j += 8)
        tile[threadIdx.y + j][threadIdx.x] = g_G[(y + j) * Dn + x];
    __syncthreads();
    x = blockIdx.y * 32 + threadIdx.x;
    y = blockIdx.x * 32 + threadIdx.y;
    #pragma unroll
    for (int j = 0; j < 32; j += 8) {
        float v = tile[threadIdx.x][threadIdx.y + j];
        bf16 h, l; split_f32(v, h, l);
        g_GTh[(y + j) * Dn + x] = h;
        g_GTl[(y + j) * Dn + x] = l;
    }
}

// ---------------------------------------------------------------------------
// mma.sync bf16 m16n8k16 (row.col)
// ---------------------------------------------------------------------------
__device__ __forceinline__ void mma_bf16(float* c, const uint32_t* a, const uint32_t* b) {
    asm volatile(
        "mma.sync.aligned.m16n8k16.row.col.f32.bf16.bf16.f32 "
        "{%0,%1,%2,%3}, {%4,%5,%6,%7}, {%8,%9}, {%0,%1,%2,%3};"
        : "+f"(c[0]), "+f"(c[1]), "+f"(c[2]), "+f"(c[3])
        : "r"(a[0]), "r"(a[1]), "r"(a[2]), "r"(a[3]), "r"(b[0]), "r"(b[1]));
}

// ---------------------------------------------------------------------------
// Chain split GEMM body (proven Round-7 code): C[i,n] = sum_k A[i,k]*B[n,k]
// ---------------------------------------------------------------------------
template <int WRITE_BF16>
__device__ __forceinline__ void gemm_split_body(
        const bf16* __restrict__ Ah, const bf16* __restrict__ Al,
        const bf16* __restrict__ Bh, const bf16* __restrict__ Bl,
        float* __restrict__ Cf, bf16* __restrict__ Ch, bf16* __restrict__ Cl) {
    constexpr int BM = 128, BK = 32;
    constexpr int PA = BK + 8;
    constexpr int MT = 4, NT = 4;

    __shared__ bf16 sAh[BM * PA];
    __shared__ bf16 sAl[BM * PA];
    __shared__ bf16 sBh[BM * PA];
    __shared__ bf16 sBl[BM * PA];

    const int i0 = blockIdx.y * BM;
    const int n0 = blockIdx.x * BM;

    const int tid  = threadIdx.x;
    const int w    = tid >> 5;
    const int lane = tid & 31;
    const int wm   = w >> 2;
    const int wn   = w & 3;
    const int gid  = lane >> 2;
    const int tig  = lane & 3;

    float acc[MT][NT][4];
    #pragma unroll
    for (int mt = 0; mt < MT; ++mt)
        #pragma unroll
        for (int nt = 0; nt < NT; ++nt)
            #pragma unroll
            for (int q = 0; q < 4; ++q) acc[mt][nt][q] = 0.f;

    for (int k0 = 0; k0 < Dn; k0 += BK) {
        #pragma unroll
        for (int l = 0; l < 2; ++l) {
            int idx = tid + l * 256;
            int row = idx >> 2, c8 = (idx & 3) * 8;
            size_t goA = (size_t)(i0 + row) * Dn + k0 + c8;
            size_t goB = (size_t)(n0 + row) * Dn + k0 + c8;
            int so = row * PA + c8;
            *reinterpret_cast<uint4*>(&sAh[so]) = *reinterpret_cast<const uint4*>(Ah + goA);
            *reinterpret_cast<uint4*>(&sAl[so]) = *reinterpret_cast<const uint4*>(Al + goA);
            *reinterpret_cast<uint4*>(&sBh[so]) = *reinterpret_cast<const uint4*>(Bh + goB);
            *reinterpret_cast<uint4*>(&sBl[so]) = *reinterpret_cast<const uint4*>(Bl + goB);
        }
        __syncthreads();

        #pragma unroll
        for (int ks = 0; ks < BK; ks += 16) {
            uint32_t bh[NT][2], bl[NT][2];
            #pragma unroll
            for (int nt = 0; nt < NT; ++nt) {
                int bn = wn * 32 + nt * 8 + gid;
                int o = bn * PA + ks + tig * 2;
                bh[nt][0] = *reinterpret_cast<const uint32_t*>(&sBh[o]);
                bh[nt][1] = *reinterpret_cast<const uint32_t*>(&sBh[o + 8]);
                bl[nt][0] = *reinterpret_cast<const uint32_t*>(&sBl[o]);
                bl[nt][1] = *reinterpret_cast<const uint32_t*>(&sBl[o + 8]);
            }
            #pragma unroll
            for (int mt = 0; mt < MT; ++mt) {
                int ar = wm * 64 + mt * 16 + gid;
                int o0 = ar * PA + ks + tig * 2, o1 = o0 + 8 * PA;
                uint32_t ah[4], al[4];
                ah[0] = *reinterpret_cast<const uint32_t*>(&sAh[o0]);
                ah[1] = *reinterpret_cast<const uint32_t*>(&sAh[o1]);
                ah[2] = *reinterpret_cast<const uint32_t*>(&sAh[o0 + 8]);
                ah[3] = *reinterpret_cast<const uint32_t*>(&sAh[o1 + 8]);
                al[0] = *reinterpret_cast<const uint32_t*>(&sAl[o0]);
                al[1] = *reinterpret_cast<const uint32_t*>(&sAl[o1]);
                al[2] = *reinterpret_cast<const uint32_t*>(&sAl[o0 + 8]);
                al[3] = *reinterpret_cast<const uint32_t*>(&sAl[o1 + 8]);
                #pragma unroll
                for (int nt = 0; nt < NT; ++nt) {
                    mma_bf16(acc[mt][nt], ah, bh[nt]);
                    mma_bf16(acc[mt][nt], ah, bl[nt]);
                    mma_bf16(acc[mt][nt], al, bh[nt]);
                }
            }
        }
        __syncthreads();
    }

    #pragma unroll
    for (int mt = 0; mt < MT; ++mt) {
        int row = i0 + wm * 64 + mt * 16 + gid;
        #pragma unroll
        for (int nt = 0; nt < NT; ++nt) {
            int col = n0 + wn * 32 + nt * 8 + tig * 2;
            if (WRITE_BF16) {
                bf16 h0, l0, h1, l1;
                split_f32(acc[mt][nt][0], h0, l0);
                split_f32(acc[mt][nt][1], h1, l1);
                *reinterpret_cast<bf162*>(Ch + (size_t)row * Dn + col) = bf162(h0, h1);
                *reinterpret_cast<bf162*>(Cl + (size_t)row * Dn + col) = bf162(l0, l1);
                split_f32(acc[mt][nt][2], h0, l0);
                split_f32(acc[mt][nt][3], h1, l1);
                *reinterpret_cast<bf162*>(Ch + (size_t)(row + 8) * Dn + col) = bf162(h0, h1);
                *reinterpret_cast<bf162*>(Cl + (size_t)(row + 8) * Dn + col) = bf162(l0, l1);
            } else {
                float2 v0 = {acc[mt][nt][0], acc[mt][nt][1]};
                float2 v1 = {acc[mt][nt][2], acc[mt][nt][3]};
                *reinterpret_cast<float2*>(Cf + (size_t)row * Dn + col) = v0;
                *reinterpret_cast<float2*>(Cf + (size_t)(row + 8) * Dn + col) = v1;
            }
        }
    }
}

__global__ void __launch_bounds__(256, 1) gemm_M_kernel() {
    gemm_split_body<1>(g_QWh, g_QWl, g_ETh, g_ETl, nullptr, g_Mh, g_Ml);
}
__global__ void __launch_bounds__(256, 1) gemm_G_kernel() {
    gemm_split_body<0>(g_Mh, g_Ml, g_Wh, g_Wl, g_G, nullptr, nullptr);
}

// ---------------------------------------------------------------------------
// Final GEMM, 2-stage cp.async pipeline:
// out[b,i,k] = sum_m A[b,i,m] * GT[k,m] + mb[k]
// BK=16, 2 stages, 48KB static smem, 2 CTAs/SM.
// ---------------------------------------------------------------------------
__global__ void __launch_bounds__(256, 2)
gemm_final_kernel(float* __restrict__ out) {
    constexpr int BK = 16;
    constexpr int PA = BK + 8;     // 24 bf16 pitch = 48B rows (16B aligned)
    constexpr int MT = 4, NT = 4;
    constexpr int NK = Dn / BK;    // 64

    __shared__ bf16 sAh[2][128 * PA];
    __shared__ bf16 sAl[2][128 * PA];
    __shared__ bf16 sBh[2][128 * PA];
    __shared__ bf16 sBl[2][128 * PA];

    const int b  = blockIdx.z;
    const int i0 = blockIdx.y * 128;
    const int n0 = blockIdx.x * 128;
    const bf16* __restrict__ Ahb = g_Ah + ((size_t)b << 20);
    const bf16* __restrict__ Alb = g_Al + ((size_t)b << 20);

    const int tid  = threadIdx.x;
    const int w    = tid >> 5;
    const int lane = tid & 31;
    const int wm   = w >> 2;
    const int wn   = w & 3;
    const int gid  = lane >> 2;
    const int tig  = lane & 3;

    // per-thread copy slot: 1x 16B chunk per array per stage
    const int crow = tid >> 1;
    const int cc8  = (tid & 1) * 8;
    const int cso  = crow * PA + cc8;
    uint32_t sAh0 = (uint32_t)__cvta_generic_to_shared(&sAh[0][cso]);
    uint32_t sAh1 = (uint32_t)__cvta_generic_to_shared(&sAh[1][cso]);
    uint32_t sAl0 = (uint32_t)__cvta_generic_to_shared(&sAl[0][cso]);
    uint32_t sAl1 = (uint32_t)__cvta_generic_to_shared(&sAl[1][cso]);
    uint32_t sBh0 = (uint32_t)__cvta_generic_to_shared(&sBh[0][cso]);
    uint32_t sBh1 = (uint32_t)__cvta_generic_to_shared(&sBh[1][cso]);
    uint32_t sBl0 = (uint32_t)__cvta_generic_to_shared(&sBl[0][cso]);
    uint32_t sBl1 = (uint32_t)__cvta_generic_to_shared(&sBl[1][cso]);
    const size_t gA = (size_t)(i0 + crow) * Dn + cc8;
    const size_t gB = (size_t)(n0 + crow) * Dn + cc8;

    float acc[MT][NT][4];
    #pragma unroll
    for (int mt = 0; mt < MT; ++mt)
        #pragma unroll
        for (int nt = 0; nt < NT; ++nt)
            #pragma unroll
            for (int q = 0; q < 4; ++q) acc[mt][nt][q] = 0.f;

    // prologue: stage 0 <- kt 0
    cp_async16(sAh0, Ahb + gA);
    cp_async16(sAl0, Alb + gA);
    cp_async16(sBh0, g_GTh + gB);
    cp_async16(sBl0, g_GTl + gB);
    cp_commit();

    for (int kt = 0; kt < NK; ++kt) {
        int st = kt & 1;
        if (kt + 1 < NK) {
            int ko = (kt + 1) * BK;
            if (st == 0) {
                cp_async16(sAh1, Ahb + gA + ko);
                cp_async16(sAl1, Alb + gA + ko);
                cp_async16(sBh1, g_GTh + gB + ko);
                cp_async16(sBl1, g_GTl + gB + ko);
            } else {
                cp_async16(sAh0, Ahb + gA + ko);
                cp_async16(sAl0, Alb + gA + ko);
                cp_async16(sBh0, g_GTh + gB + ko);
                cp_async16(sBl0, g_GTl + gB + ko);
            }
        }
        cp_commit();
        cp_wait1();            // stage kt's group complete
        __syncthreads();

        const bf16* pAh = sAh[st];
        const bf16* pAl = sAl[st];
        const bf16* pBh = sBh[st];
        const bf16* pBl = sBl[st];

        uint32_t bh[NT][2], bl[NT][2];
        #pragma unroll
        for (int nt = 0; nt < NT; ++nt) {
            int o = (wn * 32 + nt * 8 + gid) * PA + tig * 2;
            bh[nt][0] = *reinterpret_cast<const uint32_t*>(&pBh[o]);
            bh[nt][1] = *reinterpret_cast<const uint32_t*>(&pBh[o + 8]);
            bl[nt][0] = *reinterpret_cast<const uint32_t*>(&pBl[o]);
            bl[nt][1] = *reinterpret_cast<const uint32_t*>(&pBl[o + 8]);
        }
        #pragma unroll
        for (int mt = 0; mt < MT; ++mt) {
            int o0 = (wm * 64 + mt * 16 + gid) * PA + tig * 2;
            int o1 = o0 + 8 * PA;
            uint32_t ah[4], al[4];
            ah[0] = *reinterpret_cast<const uint32_t*>(&pAh[o0]);
            ah[1] = *reinterpret_cast<const uint32_t*>(&pAh[o1]);
            ah[2] = *reinterpret_cast<const uint32_t*>(&pAh[o0 + 8]);
            ah[3] = *reinterpret_cast<const uint32_t*>(&pAh[o1 + 8]);
            al[0] = *reinterpret_cast<const uint32_t*>(&pAl[o0]);
            al[1] = *reinterpret_cast<const uint32_t*>(&pAl[o1]);
            al[2] = *reinterpret_cast<const uint32_t*>(&pAl[o0 + 8]);
            al[3] = *reinterpret_cast<const uint32_t*>(&pAl[o1 + 8]);
            #pragma unroll
            for (int nt = 0; nt < NT; ++nt) {
                mma_bf16(acc[mt][nt], ah, bh[nt]);
                mma_bf16(acc[mt][nt], ah, bl[nt]);
                mma_bf16(acc[mt][nt], al, bh[nt]);
            }
        }
        __syncthreads();   // protect stage st from being overwritten next iter
    }

    float* __restrict__ outb = out + (size_t)b * Dn * Dn;
    #pragma unroll
    for (int mt = 0; mt < MT; ++mt) {
        int row = i0 + wm * 64 + mt * 16 + gid;
        #pragma unroll
        for (int nt = 0; nt < NT; ++nt) {
            int col = n0 + wn * 32 + nt * 8 + tig * 2;
            float2 mbv = *reinterpret_cast<const float2*>(&g_mb[col]);
            float2 v0 = {acc[mt][nt][0] + mbv.x, acc[mt][nt][1] + mbv.y};
            float2 v1 = {acc[mt][nt][2] + mbv.x, acc[mt][nt][3] + mbv.y};
            *reinterpret_cast<float2*>(outb + (size_t)row * Dn + col) = v0;
            *reinterpret_cast<float2*>(outb + (size_t)(row + 8) * Dn + col) = v1;
        }
    }
}

// ---------------------------------------------------------------------------
// kernel_launch — only harness pointers cross the host/device line.
// ---------------------------------------------------------------------------
extern "C" void kernel_launch(void* const* d_in, const int* in_sizes, int n_in,
                              void* d_out, int out_size) {
    const float* x  = (const float*)d_in[0];
    const float* qw = (const float*)d_in[1];
    const float* ph = (const float*)d_in[2];
    const float* em = (const float*)d_in[3];
    const float* gw = (const float*)d_in[4];
    const float* gb = (const float*)d_in[5];
    float* out = (float*)d_out;

    reduce_w_kernel<<<(Dn * Dn / 4) / 256, 256>>>(gw);
    reduce_b_kernel<<<Dn / 256, 256>>>(gb);
    cos_kernel<<<(Dn * Dn) / 256, 256>>>(ph);
    split_QW_kernel<<<(Dn * Dn / 4) / 256, 256>>>(qw);
    transpose_split_E_kernel<<<dim3(Dn / 32, Dn / 32), dim3(32, 8)>>>(em);
    split_A_kernel<<<dim3((Dn * Dn / 4) / 256, Bn), 256>>>(x);

    gemm_M_kernel<<<dim3(Dn / 128, Dn / 128), 256>>>();
    gemm_G_kernel<<<dim3(Dn / 128, Dn / 128), 256>>>();
    split_GT_kernel<<<dim3(Dn / 32, Dn / 32), dim3(32, 8)>>>();

    gemm_final_kernel<<<dim3(Dn / 128, Dn / 128, Bn), 256>>>(out);
}

// round 10
// speedup vs baseline: 1.7650x; 1.0536x over previous
#include <cuda_runtime.h>
#include <cuda_bf16.h>
#include <cstdint>

#define Dn 1024
#define Bn 16
#define Rn 100

typedef __nv_bfloat16 bf16;
typedef __nv_bfloat162 bf162;

// Scratch (device globals; no allocations allowed).
// ONLY referenced from device code (Round-6 lesson).
__device__ float g_mb[Dn];
__device__ float g_Ccos[Dn * Dn];
__device__ float g_G[Dn * Dn];
__device__ bf16 g_QWh[Dn * Dn], g_QWl[Dn * Dn];
__device__ bf16 g_ETh[Dn * Dn], g_ETl[Dn * Dn];
__device__ bf16 g_Wh[Dn * Dn],  g_Wl[Dn * Dn];
__device__ bf16 g_Mh[Dn * Dn],  g_Ml[Dn * Dn];
__device__ bf16 g_GTh[Dn * Dn], g_GTl[Dn * Dn];
__device__ bf16 g_Ah[Bn * Dn * Dn];
__device__ bf16 g_Al[Bn * Dn * Dn];

__device__ __forceinline__ void split_f32(float v, bf16& h, bf16& l) {
    h = __float2bfloat16_rn(v);
    l = __float2bfloat16_rn(v - __bfloat162float(h));
}

__device__ __forceinline__ void cp_async16(uint32_t dst_smem, const void* src) {
    asm volatile("cp.async.cg.shared.global [%0], [%1], 16;" :: "r"(dst_smem), "l"(src));
}
__device__ __forceinline__ void cp_commit() { asm volatile("cp.async.commit_group;"); }
__device__ __forceinline__ void cp_wait1() { asm volatile("cp.async.wait_group 1;"); }

__device__ __forceinline__ uint32_t smem_u32(const void* p) {
    uint32_t a;
    asm("{ .reg .u64 t; cvta.to.shared.u64 t, %1; cvt.u32.u64 %0, t; }" : "=r"(a) : "l"(p));
    return a;
}

// ldmatrix: 4x 8x8 b16 matrices, one row address per lane
__device__ __forceinline__ void ldsm_x4(uint32_t& r0, uint32_t& r1, uint32_t& r2, uint32_t& r3,
                                        uint32_t addr) {
    asm volatile("ldmatrix.sync.aligned.m8n8.x4.shared.b16 {%0,%1,%2,%3}, [%4];"
                 : "=r"(r0), "=r"(r1), "=r"(r2), "=r"(r3) : "r"(addr));
}

// ---------------------------------------------------------------------------
// Prework kernels (proven)
// ---------------------------------------------------------------------------
__global__ void reduce_w_kernel(const float* __restrict__ gw) {
    int i4 = blockIdx.x * blockDim.x + threadIdx.x;
    const float4* p = reinterpret_cast<const float4*>(gw);
    float ax = 0.f, ay = 0.f, az = 0.f, aw = 0.f;
    #pragma unroll 4
    for (int r = 0; r < Rn; ++r) {
        float4 v = p[(size_t)r * (Dn * Dn / 4) + i4];
        ax += v.x; ay += v.y; az += v.z; aw += v.w;
    }
    const float inv = 1.0f / (float)Rn;
    float vv[4] = {ax * inv, ay * inv, az * inv, aw * inv};
    bf16 h[4], l[4];
    #pragma unroll
    for (int q = 0; q < 4; ++q) split_f32(vv[q], h[q], l[q]);
    reinterpret_cast<bf162*>(g_Wh)[i4 * 2]     = bf162(h[0], h[1]);
    reinterpret_cast<bf162*>(g_Wh)[i4 * 2 + 1] = bf162(h[2], h[3]);
    reinterpret_cast<bf162*>(g_Wl)[i4 * 2]     = bf162(l[0], l[1]);
    reinterpret_cast<bf162*>(g_Wl)[i4 * 2 + 1] = bf162(l[2], l[3]);
}

__global__ void reduce_b_kernel(const float* __restrict__ gb) {
    int k = blockIdx.x * blockDim.x + threadIdx.x;
    float acc = 0.f;
    #pragma unroll 4
    for (int r = 0; r < Rn; ++r) acc += gb[r * Dn + k];
    g_mb[k] = acc / (float)Rn;
}

__global__ void cos_kernel(const float* __restrict__ ph) {
    int i = blockIdx.x * blockDim.x + threadIdx.x;
    g_Ccos[i] = cosf(ph[i]);
}

__global__ void split_QW_kernel(const float* __restrict__ qw) {
    int i4 = blockIdx.x * blockDim.x + threadIdx.x;
    float4 v = reinterpret_cast<const float4*>(qw)[i4];
    float vv[4] = {v.x, v.y, v.z, v.w};
    bf16 h[4], l[4];
    #pragma unroll
    for (int q = 0; q < 4; ++q) split_f32(vv[q], h[q], l[q]);
    reinterpret_cast<bf162*>(g_QWh)[i4 * 2]     = bf162(h[0], h[1]);
    reinterpret_cast<bf162*>(g_QWh)[i4 * 2 + 1] = bf162(h[2], h[3]);
    reinterpret_cast<bf162*>(g_QWl)[i4 * 2]     = bf162(l[0], l[1]);
    reinterpret_cast<bf162*>(g_QWl)[i4 * 2 + 1] = bf162(l[2], l[3]);
}

__global__ void split_A_kernel(const float* __restrict__ x) {
    int b = blockIdx.y;
    int i4 = blockIdx.x * blockDim.x + threadIdx.x;
    float4 cv = reinterpret_cast<const float4*>(g_Ccos)[i4];
    int m = (i4 * 4) & (Dn - 1);
    float4 xv = *reinterpret_cast<const float4*>(x + (size_t)b * Dn + m);
    float vv[4] = {cv.x * xv.x, cv.y * xv.y, cv.z * xv.z, cv.w * xv.w};
    bf16 h[4], l[4];
    #pragma unroll
    for (int q = 0; q < 4; ++q) split_f32(vv[q], h[q], l[q]);
    size_t o2 = ((size_t)b << 19) + (size_t)i4 * 2;
    reinterpret_cast<bf162*>(g_Ah)[o2]     = bf162(h[0], h[1]);
    reinterpret_cast<bf162*>(g_Ah)[o2 + 1] = bf162(h[2], h[3]);
    reinterpret_cast<bf162*>(g_Al)[o2]     = bf162(l[0], l[1]);
    reinterpret_cast<bf162*>(g_Al)[o2 + 1] = bf162(l[2], l[3]);
}

__global__ void transpose_split_E_kernel(const float* __restrict__ in) {
    __shared__ float tile[32][33];
    int x = blockIdx.x * 32 + threadIdx.x;
    int y = blockIdx.y * 32 + threadIdx.y;
    #pragma unroll
    for (int j = 0; j < 32; j += 8)
        tile[threadIdx.y + j][threadIdx.x] = in[(y + j) * Dn + x];
    __syncthreads();
    x = blockIdx.y * 32 + threadIdx.x;
    y = blockIdx.x * 32 + threadIdx.y;
    #pragma unroll
    for (int j = 0; j < 32; j += 8) {
        float v = tile[threadIdx.x][threadIdx.y + j];
        bf16 h, l; split_f32(v, h, l);
        g_ETh[(y + j) * Dn + x] = h;
        g_ETl[(y + j) * Dn + x] = l;
    }
}

__global__ void split_GT_kernel() {
    __shared__ float tile[32][33];
    int x = blockIdx.x * 32 + threadIdx.x;
    int y = blockIdx.y * 32 + threadIdx.y;
    #pragma unroll
    for (int j = 0; j < 32; j += 8)
        tile[threadIdx.y + j][threadIdx.x] = g_G[(y + j) * Dn + x];
    __syncthreads();
    x = blockIdx.y * 32 + threadIdx.x;
    y = blockIdx.x * 32 + threadIdx.y;
    #pragma unroll
    for (int j = 0; j < 32; j += 8) {
        float v = tile[threadIdx.x][threadIdx.y + j];
        bf16 h, l; split_f32(v, h, l);
        g_GTh[(y + j) * Dn + x] = h;
        g_GTl[(y + j) * Dn + x] = l;
    }
}

// ---------------------------------------------------------------------------
// mma.sync bf16 m16n8k16 (row.col)
// ---------------------------------------------------------------------------
__device__ __forceinline__ void mma_bf16(float* c, const uint32_t* a, const uint32_t* b) {
    asm volatile(
        "mma.sync.aligned.m16n8k16.row.col.f32.bf16.bf16.f32 "
        "{%0,%1,%2,%3}, {%4,%5,%6,%7}, {%8,%9}, {%0,%1,%2,%3};"
        : "+f"(c[0]), "+f"(c[1]), "+f"(c[2]), "+f"(c[3])
        : "r"(a[0]), "r"(a[1]), "r"(a[2]), "r"(a[3]), "r"(b[0]), "r"(b[1]));
}

// ---------------------------------------------------------------------------
// Chain split GEMM body (proven): C[i,n] = sum_k A[i,k]*B[n,k]
// ---------------------------------------------------------------------------
template <int WRITE_BF16>
__device__ __forceinline__ void gemm_split_body(
        const bf16* __restrict__ Ah, const bf16* __restrict__ Al,
        const bf16* __restrict__ Bh, const bf16* __restrict__ Bl,
        float* __restrict__ Cf, bf16* __restrict__ Ch, bf16* __restrict__ Cl) {
    constexpr int BM = 128, BK = 32;
    constexpr int PA = BK + 8;
    constexpr int MT = 4, NT = 4;

    __shared__ bf16 sAh[BM * PA];
    __shared__ bf16 sAl[BM * PA];
    __shared__ bf16 sBh[BM * PA];
    __shared__ bf16 sBl[BM * PA];

    const int i0 = blockIdx.y * BM;
    const int n0 = blockIdx.x * BM;

    const int tid  = threadIdx.x;
    const int w    = tid >> 5;
    const int lane = tid & 31;
    const int wm   = w >> 2;
    const int wn   = w & 3;
    const int gid  = lane >> 2;
    const int tig  = lane & 3;

    float acc[MT][NT][4];
    #pragma unroll
    for (int mt = 0; mt < MT; ++mt)
        #pragma unroll
        for (int nt = 0; nt < NT; ++nt)
            #pragma unroll
            for (int q = 0; q < 4; ++q) acc[mt][nt][q] = 0.f;

    for (int k0 = 0; k0 < Dn; k0 += BK) {
        #pragma unroll
        for (int l = 0; l < 2; ++l) {
            int idx = tid + l * 256;
            int row = idx >> 2, c8 = (idx & 3) * 8;
            size_t goA = (size_t)(i0 + row) * Dn + k0 + c8;
            size_t goB = (size_t)(n0 + row) * Dn + k0 + c8;
            int so = row * PA + c8;
            *reinterpret_cast<uint4*>(&sAh[so]) = *reinterpret_cast<const uint4*>(Ah + goA);
            *reinterpret_cast<uint4*>(&sAl[so]) = *reinterpret_cast<const uint4*>(Al + goA);
            *reinterpret_cast<uint4*>(&sBh[so]) = *reinterpret_cast<const uint4*>(Bh + goB);
            *reinterpret_cast<uint4*>(&sBl[so]) = *reinterpret_cast<const uint4*>(Bl + goB);
        }
        __syncthreads();

        #pragma unroll
        for (int ks = 0; ks < BK; ks += 16) {
            uint32_t bh[NT][2], bl[NT][2];
            #pragma unroll
            for (int nt = 0; nt < NT; ++nt) {
                int bn = wn * 32 + nt * 8 + gid;
                int o = bn * PA + ks + tig * 2;
                bh[nt][0] = *reinterpret_cast<const uint32_t*>(&sBh[o]);
                bh[nt][1] = *reinterpret_cast<const uint32_t*>(&sBh[o + 8]);
                bl[nt][0] = *reinterpret_cast<const uint32_t*>(&sBl[o]);
                bl[nt][1] = *reinterpret_cast<const uint32_t*>(&sBl[o + 8]);
            }
            #pragma unroll
            for (int mt = 0; mt < MT; ++mt) {
                int ar = wm * 64 + mt * 16 + gid;
                int o0 = ar * PA + ks + tig * 2, o1 = o0 + 8 * PA;
                uint32_t ah[4], al[4];
                ah[0] = *reinterpret_cast<const uint32_t*>(&sAh[o0]);
                ah[1] = *reinterpret_cast<const uint32_t*>(&sAh[o1]);
                ah[2] = *reinterpret_cast<const uint32_t*>(&sAh[o0 + 8]);
                ah[3] = *reinterpret_cast<const uint32_t*>(&sAh[o1 + 8]);
                al[0] = *reinterpret_cast<const uint32_t*>(&sAl[o0]);
                al[1] = *reinterpret_cast<const uint32_t*>(&sAl[o1]);
                al[2] = *reinterpret_cast<const uint32_t*>(&sAl[o0 + 8]);
                al[3] = *reinterpret_cast<const uint32_t*>(&sAl[o1 + 8]);
                #pragma unroll
                for (int nt = 0; nt < NT; ++nt) {
                    mma_bf16(acc[mt][nt], ah, bh[nt]);
                    mma_bf16(acc[mt][nt], ah, bl[nt]);
                    mma_bf16(acc[mt][nt], al, bh[nt]);
                }
            }
        }
        __syncthreads();
    }

    #pragma unroll
    for (int mt = 0; mt < MT; ++mt) {
        int row = i0 + wm * 64 + mt * 16 + gid;
        #pragma unroll
        for (int nt = 0; nt < NT; ++nt) {
            int col = n0 + wn * 32 + nt * 8 + tig * 2;
            if (WRITE_BF16) {
                bf16 h0, l0, h1, l1;
                split_f32(acc[mt][nt][0], h0, l0);
                split_f32(acc[mt][nt][1], h1, l1);
                *reinterpret_cast<bf162*>(Ch + (size_t)row * Dn + col) = bf162(h0, h1);
                *reinterpret_cast<bf162*>(Cl + (size_t)row * Dn + col) = bf162(l0, l1);
                split_f32(acc[mt][nt][2], h0, l0);
                split_f32(acc[mt][nt][3], h1, l1);
                *reinterpret_cast<bf162*>(Ch + (size_t)(row + 8) * Dn + col) = bf162(h0, h1);
                *reinterpret_cast<bf162*>(Cl + (size_t)(row + 8) * Dn + col) = bf162(l0, l1);
            } else {
                float2 v0 = {acc[mt][nt][0], acc[mt][nt][1]};
                float2 v1 = {acc[mt][nt][2], acc[mt][nt][3]};
                *reinterpret_cast<float2*>(Cf + (size_t)row * Dn + col) = v0;
                *reinterpret_cast<float2*>(Cf + (size_t)(row + 8) * Dn + col) = v1;
            }
        }
    }
}

__global__ void __launch_bounds__(256, 1) gemm_M_kernel() {
    gemm_split_body<1>(g_QWh, g_QWl, g_ETh, g_ETl, nullptr, g_Mh, g_Ml);
}
__global__ void __launch_bounds__(256, 1) gemm_G_kernel() {
    gemm_split_body<0>(g_Mh, g_Ml, g_Wh, g_Wl, g_G, nullptr, nullptr);
}

// ---------------------------------------------------------------------------
// Final GEMM, 2-stage cp.async pipeline + ldmatrix fragment loads:
// out[b,i,k] = sum_m A[b,i,m] * GT[k,m] + mb[k]
// BK=16, 2 stages, 48KB static smem, 2 CTAs/SM.
// ---------------------------------------------------------------------------
__global__ void __launch_bounds__(256, 2)
gemm_final_kernel(float* __restrict__ out) {
    constexpr int BK = 16;
    constexpr int PA = BK + 8;       // 24 bf16 = 48B pitch (16B-aligned rows)
    constexpr int PAB = PA * 2;      // 48 bytes
    constexpr int MT = 4, NT = 4;
    constexpr int NK = Dn / BK;      // 64

    __shared__ bf16 sAh[2][128 * PA];
    __shared__ bf16 sAl[2][128 * PA];
    __shared__ bf16 sBh[2][128 * PA];
    __shared__ bf16 sBl[2][128 * PA];

    const int b  = blockIdx.z;
    const int i0 = blockIdx.y * 128;
    const int n0 = blockIdx.x * 128;
    const bf16* __restrict__ Ahb = g_Ah + ((size_t)b << 20);
    const bf16* __restrict__ Alb = g_Al + ((size_t)b << 20);

    const int tid  = threadIdx.x;
    const int w    = tid >> 5;
    const int lane = tid & 31;
    const int wm   = w >> 2;
    const int wn   = w & 3;
    const int gid  = lane >> 2;
    const int tig  = lane & 3;

    // --- cp.async copy slots: 1x 16B per array per stage per thread ---
    const int crow = tid >> 1;
    const int cc8  = (tid & 1) * 8;
    const int cso  = crow * PA + cc8;
    uint32_t sAh0 = smem_u32(&sAh[0][cso]);
    uint32_t sAh1 = smem_u32(&sAh[1][cso]);
    uint32_t sAl0 = smem_u32(&sAl[0][cso]);
    uint32_t sAl1 = smem_u32(&sAl[1][cso]);
    uint32_t sBh0 = smem_u32(&sBh[0][cso]);
    uint32_t sBh1 = smem_u32(&sBh[1][cso]);
    uint32_t sBl0 = smem_u32(&sBl[0][cso]);
    uint32_t sBl1 = smem_u32(&sBl[1][cso]);
    const size_t gA = (size_t)(i0 + crow) * Dn + cc8;
    const size_t gB = (size_t)(n0 + crow) * Dn + cc8;

    // --- ldmatrix per-lane addresses ---
    // A (x4 = one m16xk16 tile): lane L -> row (L&15), k-half (L>>4)
    const uint32_t aOff = (uint32_t)((wm * 64 + (lane & 15)) * PAB + (lane >> 4) * 16);
    // B (x4 = two n8xk16 tiles): lane L -> row (L&7) + ((L>>4)<<3), k-half ((L>>3)&1)
    const uint32_t bOff = (uint32_t)((wn * 32 + (lane & 7) + ((lane >> 4) << 3)) * PAB
                                     + ((lane >> 3) & 1) * 16);
    uint32_t aH0 = smem_u32(&sAh[0][0]) + aOff, aH1 = smem_u32(&sAh[1][0]) + aOff;
    uint32_t aL0 = smem_u32(&sAl[0][0]) + aOff, aL1 = smem_u32(&sAl[1][0]) + aOff;
    uint32_t bH0 = smem_u32(&sBh[0][0]) + bOff, bH1 = smem_u32(&sBh[1][0]) + bOff;
    uint32_t bL0 = smem_u32(&sBl[0][0]) + bOff, bL1 = smem_u32(&sBl[1][0]) + bOff;

    float acc[MT][NT][4];
    #pragma unroll
    for (int mt = 0; mt < MT; ++mt)
        #pragma unroll
        for (int nt = 0; nt < NT; ++nt)
            #pragma unroll
            for (int q = 0; q < 4; ++q) acc[mt][nt][q] = 0.f;

    // prologue: stage 0 <- kt 0
    cp_async16(sAh0, Ahb + gA);
    cp_async16(sAl0, Alb + gA);
    cp_async16(sBh0, g_GTh + gB);
    cp_async16(sBl0, g_GTl + gB);
    cp_commit();

    for (int kt = 0; kt < NK; ++kt) {
        int st = kt & 1;
        if (kt + 1 < NK) {
            int ko = (kt + 1) * BK;
            if (st == 0) {
                cp_async16(sAh1, Ahb + gA + ko);
                cp_async16(sAl1, Alb + gA + ko);
                cp_async16(sBh1, g_GTh + gB + ko);
                cp_async16(sBl1, g_GTl + gB + ko);
            } else {
                cp_async16(sAh0, Ahb + gA + ko);
                cp_async16(sAl0, Alb + gA + ko);
                cp_async16(sBh0, g_GTh + gB + ko);
                cp_async16(sBl0, g_GTl + gB + ko);
            }
        }
        cp_commit();
        cp_wait1();
        __syncthreads();

        const uint32_t aH = st ? aH1 : aH0;
        const uint32_t aL = st ? aL1 : aL0;
        const uint32_t bH = st ? bH1 : bH0;
        const uint32_t bL = st ? bL1 : bL0;

        // B fragments: 2 ldmatrix.x4 per hi/lo (each covers nt pair)
        uint32_t bh[NT][2], bl[NT][2];
        #pragma unroll
        for (int j = 0; j < 2; ++j) {
            uint32_t r0, r1, r2, r3;
            ldsm_x4(r0, r1, r2, r3, bH + j * 16 * PAB);
            bh[2 * j][0] = r0; bh[2 * j][1] = r1;
            bh[2 * j + 1][0] = r2; bh[2 * j + 1][1] = r3;
            ldsm_x4(r0, r1, r2, r3, bL + j * 16 * PAB);
            bl[2 * j][0] = r0; bl[2 * j][1] = r1;
            bl[2 * j + 1][0] = r2; bl[2 * j + 1][1] = r3;
        }
        #pragma unroll
        for (int mt = 0; mt < MT; ++mt) {
            uint32_t ah[4], al[4];
            ldsm_x4(ah[0], ah[1], ah[2], ah[3], aH + mt * 16 * PAB);
            ldsm_x4(al[0], al[1], al[2], al[3], aL + mt * 16 * PAB);
            #pragma unroll
            for (int nt = 0; nt < NT; ++nt) {
                mma_bf16(acc[mt][nt], ah, bh[nt]);
                mma_bf16(acc[mt][nt], ah, bl[nt]);
                mma_bf16(acc[mt][nt], al, bh[nt]);
            }
        }
        __syncthreads();
    }

    float* __restrict__ outb = out + (size_t)b * Dn * Dn;
    #pragma unroll
    for (int mt = 0; mt < MT; ++mt) {
        int row = i0 + wm * 64 + mt * 16 + gid;
        #pragma unroll
        for (int nt = 0; nt < NT; ++nt) {
            int col = n0 + wn * 32 + nt * 8 + tig * 2;
            float2 mbv = *reinterpret_cast<const float2*>(&g_mb[col]);
            float2 v0 = {acc[mt][nt][0] + mbv.x, acc[mt][nt][1] + mbv.y};
            float2 v1 = {acc[mt][nt][2] + mbv.x, acc[mt][nt][3] + mbv.y};
            *reinterpret_cast<float2*>(outb + (size_t)row * Dn + col) = v0;
            *reinterpret_cast<float2*>(outb + (size_t)(row + 8) * Dn + col) = v1;
        }
    }
}

// ---------------------------------------------------------------------------
// kernel_launch — only harness pointers cross the host/device line.
// ---------------------------------------------------------------------------
extern "C" void kernel_launch(void* const* d_in, const int* in_sizes, int n_in,
                              void* d_out, int out_size) {
    const float* x  = (const float*)d_in[0];
    const float* qw = (const float*)d_in[1];
    const float* ph = (const float*)d_in[2];
    const float* em = (const float*)d_in[3];
    const float* gw = (const float*)d_in[4];
    const float* gb = (const float*)d_in[5];
    float* out = (float*)d_out;

    reduce_w_kernel<<<(Dn * Dn / 4) / 256, 256>>>(gw);
    reduce_b_kernel<<<Dn / 256, 256>>>(gb);
    cos_kernel<<<(Dn * Dn) / 256, 256>>>(ph);
    split_QW_kernel<<<(Dn * Dn / 4) / 256, 256>>>(qw);
    transpose_split_E_kernel<<<dim3(Dn / 32, Dn / 32), dim3(32, 8)>>>(em);
    split_A_kernel<<<dim3((Dn * Dn / 4) / 256, Bn), 256>>>(x);

    gemm_M_kernel<<<dim3(Dn / 128, Dn / 128), 256>>>();
    gemm_G_kernel<<<dim3(Dn / 128, Dn / 128), 256>>>();
    split_GT_kernel<<<dim3(Dn / 32, Dn / 32), dim3(32, 8)>>>();

    gemm_final_kernel<<<dim3(Dn / 128, Dn / 128, Bn), 256>>>(out);
}

// round 11
// speedup vs baseline: 1.8310x; 1.0374x over previous
#include <cuda_runtime.h>
#include <cuda_bf16.h>
#include <cstdint>

#define Dn 1024
#define Bn 16
#define Rn 100

typedef __nv_bfloat16 bf16;
typedef __nv_bfloat162 bf162;

// Scratch (device globals; no allocations allowed).
// ONLY referenced from device code (Round-6 lesson).
__device__ float g_mb[Dn];
__device__ bf16 g_QWh[Dn * Dn], g_QWl[Dn * Dn];
__device__ bf16 g_ETh[Dn * Dn], g_ETl[Dn * Dn];
__device__ bf16 g_Wh[Dn * Dn],  g_Wl[Dn * Dn];
__device__ bf16 g_Mh[Dn * Dn],  g_Ml[Dn * Dn];
__device__ bf16 g_GTh[Dn * Dn], g_GTl[Dn * Dn];
__device__ bf16 g_Ah[Bn * Dn * Dn];
__device__ bf16 g_Al[Bn * Dn * Dn];

__device__ __forceinline__ void split_f32(float v, bf16& h, bf16& l) {
    h = __float2bfloat16_rn(v);
    l = __float2bfloat16_rn(v - __bfloat162float(h));
}

__device__ __forceinline__ void cp_async16(uint32_t dst_smem, const void* src) {
    asm volatile("cp.async.cg.shared.global [%0], [%1], 16;" :: "r"(dst_smem), "l"(src));
}
__device__ __forceinline__ void cp_commit() { asm volatile("cp.async.commit_group;"); }
__device__ __forceinline__ void cp_wait1() { asm volatile("cp.async.wait_group 1;"); }

__device__ __forceinline__ uint32_t smem_u32(const void* p) {
    uint32_t a;
    asm("{ .reg .u64 t; cvta.to.shared.u64 t, %1; cvt.u32.u64 %0, t; }" : "=r"(a) : "l"(p));
    return a;
}

__device__ __forceinline__ void ldsm_x4(uint32_t& r0, uint32_t& r1, uint32_t& r2, uint32_t& r3,
                                        uint32_t addr) {
    asm volatile("ldmatrix.sync.aligned.m8n8.x4.shared.b16 {%0,%1,%2,%3}, [%4];"
                 : "=r"(r0), "=r"(r1), "=r"(r2), "=r"(r3) : "r"(addr));
}

// ---------------------------------------------------------------------------
// Prework kernels
// ---------------------------------------------------------------------------
__global__ void reduce_w_kernel(const float* __restrict__ gw) {
    int i4 = blockIdx.x * blockDim.x + threadIdx.x;
    const float4* p = reinterpret_cast<const float4*>(gw);
    float ax = 0.f, ay = 0.f, az = 0.f, aw = 0.f;
    #pragma unroll 4
    for (int r = 0; r < Rn; ++r) {
        float4 v = p[(size_t)r * (Dn * Dn / 4) + i4];
        ax += v.x; ay += v.y; az += v.z; aw += v.w;
    }
    const float inv = 1.0f / (float)Rn;
    float vv[4] = {ax * inv, ay * inv, az * inv, aw * inv};
    bf16 h[4], l[4];
    #pragma unroll
    for (int q = 0; q < 4; ++q) split_f32(vv[q], h[q], l[q]);
    reinterpret_cast<bf162*>(g_Wh)[i4 * 2]     = bf162(h[0], h[1]);
    reinterpret_cast<bf162*>(g_Wh)[i4 * 2 + 1] = bf162(h[2], h[3]);
    reinterpret_cast<bf162*>(g_Wl)[i4 * 2]     = bf162(l[0], l[1]);
    reinterpret_cast<bf162*>(g_Wl)[i4 * 2 + 1] = bf162(l[2], l[3]);
}

__global__ void reduce_b_kernel(const float* __restrict__ gb) {
    int k = blockIdx.x * blockDim.x + threadIdx.x;
    float acc = 0.f;
    #pragma unroll 4
    for (int r = 0; r < Rn; ++r) acc += gb[r * Dn + k];
    g_mb[k] = acc / (float)Rn;
}

__global__ void split_QW_kernel(const float* __restrict__ qw) {
    int i4 = blockIdx.x * blockDim.x + threadIdx.x;
    float4 v = reinterpret_cast<const float4*>(qw)[i4];
    float vv[4] = {v.x, v.y, v.z, v.w};
    bf16 h[4], l[4];
    #pragma unroll
    for (int q = 0; q < 4; ++q) split_f32(vv[q], h[q], l[q]);
    reinterpret_cast<bf162*>(g_QWh)[i4 * 2]     = bf162(h[0], h[1]);
    reinterpret_cast<bf162*>(g_QWh)[i4 * 2 + 1] = bf162(h[2], h[3]);
    reinterpret_cast<bf162*>(g_QWl)[i4 * 2]     = bf162(l[0], l[1]);
    reinterpret_cast<bf162*>(g_QWl)[i4 * 2 + 1] = bf162(l[2], l[3]);
}

// A[b,i,m] = cos(ph[i,m]) * x[b,m] -> bf16 hi/lo (cos fused in; Ccos eliminated)
__global__ void split_A_kernel(const float* __restrict__ x, const float* __restrict__ ph) {
    int b = blockIdx.y;
    int i4 = blockIdx.x * blockDim.x + threadIdx.x;
    float4 pv = reinterpret_cast<const float4*>(ph)[i4];
    int m = (i4 * 4) & (Dn - 1);
    float4 xv = *reinterpret_cast<const float4*>(x + (size_t)b * Dn + m);
    float vv[4] = {cosf(pv.x) * xv.x, cosf(pv.y) * xv.y,
                   cosf(pv.z) * xv.z, cosf(pv.w) * xv.w};
    bf16 h[4], l[4];
    #pragma unroll
    for (int q = 0; q < 4; ++q) split_f32(vv[q], h[q], l[q]);
    size_t o2 = ((size_t)b << 19) + (size_t)i4 * 2;
    reinterpret_cast<bf162*>(g_Ah)[o2]     = bf162(h[0], h[1]);
    reinterpret_cast<bf162*>(g_Ah)[o2 + 1] = bf162(h[2], h[3]);
    reinterpret_cast<bf162*>(g_Al)[o2]     = bf162(l[0], l[1]);
    reinterpret_cast<bf162*>(g_Al)[o2 + 1] = bf162(l[2], l[3]);
}

__global__ void transpose_split_E_kernel(const float* __restrict__ in) {
    __shared__ float tile[32][33];
    int x = blockIdx.x * 32 + threadIdx.x;
    int y = blockIdx.y * 32 + threadIdx.y;
    #pragma unroll
    for (int j = 0; j < 32; j += 8)
        tile[threadIdx.y + j][threadIdx.x] = in[(y + j) * Dn + x];
    __syncthreads();
    x = blockIdx.y * 32 + threadIdx.x;
    y = blockIdx.x * 32 + threadIdx.y;
    #pragma unroll
    for (int j = 0; j < 32; j += 8) {
        float v = tile[threadIdx.x][threadIdx.y + j];
        bf16 h, l; split_f32(v, h, l);
        g_ETh[(y + j) * Dn + x] = h;
        g_ETl[(y + j) * Dn + x] = l;
    }
}

// ---------------------------------------------------------------------------
// mma.sync bf16 m16n8k16 (row.col)
// ---------------------------------------------------------------------------
__device__ __forceinline__ void mma_bf16(float* c, const uint32_t* a, const uint32_t* b) {
    asm volatile(
        "mma.sync.aligned.m16n8k16.row.col.f32.bf16.bf16.f32 "
        "{%0,%1,%2,%3}, {%4,%5,%6,%7}, {%8,%9}, {%0,%1,%2,%3};"
        : "+f"(c[0]), "+f"(c[1]), "+f"(c[2]), "+f"(c[3])
        : "r"(a[0]), "r"(a[1]), "r"(a[2]), "r"(a[3]), "r"(b[0]), "r"(b[1]));
}

// ---------------------------------------------------------------------------
// Chain split GEMM body (proven): C[i,n] = sum_k A[i,k]*B[n,k]
// ---------------------------------------------------------------------------
template <int WRITE_BF16>
__device__ __forceinline__ void gemm_split_body(
        const bf16* __restrict__ Ah, const bf16* __restrict__ Al,
        const bf16* __restrict__ Bh, const bf16* __restrict__ Bl,
        float* __restrict__ Cf, bf16* __restrict__ Ch, bf16* __restrict__ Cl) {
    constexpr int BM = 128, BK = 32;
    constexpr int PA = BK + 8;
    constexpr int MT = 4, NT = 4;

    __shared__ bf16 sAh[BM * PA];
    __shared__ bf16 sAl[BM * PA];
    __shared__ bf16 sBh[BM * PA];
    __shared__ bf16 sBl[BM * PA];

    const int i0 = blockIdx.y * BM;
    const int n0 = blockIdx.x * BM;

    const int tid  = threadIdx.x;
    const int w    = tid >> 5;
    const int lane = tid & 31;
    const int wm   = w >> 2;
    const int wn   = w & 3;
    const int gid  = lane >> 2;
    const int tig  = lane & 3;

    float acc[MT][NT][4];
    #pragma unroll
    for (int mt = 0; mt < MT; ++mt)
        #pragma unroll
        for (int nt = 0; nt < NT; ++nt)
            #pragma unroll
            for (int q = 0; q < 4; ++q) acc[mt][nt][q] = 0.f;

    for (int k0 = 0; k0 < Dn; k0 += BK) {
        #pragma unroll
        for (int l = 0; l < 2; ++l) {
            int idx = tid + l * 256;
            int row = idx >> 2, c8 = (idx & 3) * 8;
            size_t goA = (size_t)(i0 + row) * Dn + k0 + c8;
            size_t goB = (size_t)(n0 + row) * Dn + k0 + c8;
            int so = row * PA + c8;
            *reinterpret_cast<uint4*>(&sAh[so]) = *reinterpret_cast<const uint4*>(Ah + goA);
            *reinterpret_cast<uint4*>(&sAl[so]) = *reinterpret_cast<const uint4*>(Al + goA);
            *reinterpret_cast<uint4*>(&sBh[so]) = *reinterpret_cast<const uint4*>(Bh + goB);
            *reinterpret_cast<uint4*>(&sBl[so]) = *reinterpret_cast<const uint4*>(Bl + goB);
        }
        __syncthreads();

        #pragma unroll
        for (int ks = 0; ks < BK; ks += 16) {
            uint32_t bh[NT][2], bl[NT][2];
            #pragma unroll
            for (int nt = 0; nt < NT; ++nt) {
                int bn = wn * 32 + nt * 8 + gid;
                int o = bn * PA + ks + tig * 2;
                bh[nt][0] = *reinterpret_cast<const uint32_t*>(&sBh[o]);
                bh[nt][1] = *reinterpret_cast<const uint32_t*>(&sBh[o + 8]);
                bl[nt][0] = *reinterpret_cast<const uint32_t*>(&sBl[o]);
                bl[nt][1] = *reinterpret_cast<const uint32_t*>(&sBl[o + 8]);
            }
            #pragma unroll
            for (int mt = 0; mt < MT; ++mt) {
                int ar = wm * 64 + mt * 16 + gid;
                int o0 = ar * PA + ks + tig * 2, o1 = o0 + 8 * PA;
                uint32_t ah[4], al[4];
                ah[0] = *reinterpret_cast<const uint32_t*>(&sAh[o0]);
                ah[1] = *reinterpret_cast<const uint32_t*>(&sAh[o1]);
                ah[2] = *reinterpret_cast<const uint32_t*>(&sAh[o0 + 8]);
                ah[3] = *reinterpret_cast<const uint32_t*>(&sAh[o1 + 8]);
                al[0] = *reinterpret_cast<const uint32_t*>(&sAl[o0]);
                al[1] = *reinterpret_cast<const uint32_t*>(&sAl[o1]);
                al[2] = *reinterpret_cast<const uint32_t*>(&sAl[o0 + 8]);
                al[3] = *reinterpret_cast<const uint32_t*>(&sAl[o1 + 8]);
                #pragma unroll
                for (int nt = 0; nt < NT; ++nt) {
                    mma_bf16(acc[mt][nt], ah, bh[nt]);
                    mma_bf16(acc[mt][nt], ah, bl[nt]);
                    mma_bf16(acc[mt][nt], al, bh[nt]);
                }
            }
        }
        __syncthreads();
    }

    #pragma unroll
    for (int mt = 0; mt < MT; ++mt) {
        int row = i0 + wm * 64 + mt * 16 + gid;
        #pragma unroll
        for (int nt = 0; nt < NT; ++nt) {
            int col = n0 + wn * 32 + nt * 8 + tig * 2;
            if (WRITE_BF16) {
                bf16 h0, l0, h1, l1;
                split_f32(acc[mt][nt][0], h0, l0);
                split_f32(acc[mt][nt][1], h1, l1);
                *reinterpret_cast<bf162*>(Ch + (size_t)row * Dn + col) = bf162(h0, h1);
                *reinterpret_cast<bf162*>(Cl + (size_t)row * Dn + col) = bf162(l0, l1);
                split_f32(acc[mt][nt][2], h0, l0);
                split_f32(acc[mt][nt][3], h1, l1);
                *reinterpret_cast<bf162*>(Ch + (size_t)(row + 8) * Dn + col) = bf162(h0, h1);
                *reinterpret_cast<bf162*>(Cl + (size_t)(row + 8) * Dn + col) = bf162(l0, l1);
            } else {
                float2 v0 = {acc[mt][nt][0], acc[mt][nt][1]};
                float2 v1 = {acc[mt][nt][2], acc[mt][nt][3]};
                *reinterpret_cast<float2*>(Cf + (size_t)row * Dn + col) = v0;
                *reinterpret_cast<float2*>(Cf + (size_t)(row + 8) * Dn + col) = v1;
            }
        }
    }
}

__global__ void __launch_bounds__(256, 1) gemm_M_kernel() {
    gemm_split_body<1>(g_QWh, g_QWl, g_ETh, g_ETl, nullptr, g_Mh, g_Ml);
}
// G^T directly: C[k,m] = sum_j Wsum[k,j]*M[m,j]  (operands swapped; same 3 terms)
__global__ void __launch_bounds__(256, 1) gemm_GT_kernel() {
    gemm_split_body<1>(g_Wh, g_Wl, g_Mh, g_Ml, nullptr, g_GTh, g_GTl);
}

// ---------------------------------------------------------------------------
// Final GEMM (byte-identical to proven R10): 2-stage cp.async + ldmatrix
// out[b,i,k] = sum_m A[b,i,m] * GT[k,m] + mb[k]
// ---------------------------------------------------------------------------
__global__ void __launch_bounds__(256, 2)
gemm_final_kernel(float* __restrict__ out) {
    constexpr int BK = 16;
    constexpr int PA = BK + 8;
    constexpr int PAB = PA * 2;
    constexpr int MT = 4, NT = 4;
    constexpr int NK = Dn / BK;

    __shared__ bf16 sAh[2][128 * PA];
    __shared__ bf16 sAl[2][128 * PA];
    __shared__ bf16 sBh[2][128 * PA];
    __shared__ bf16 sBl[2][128 * PA];

    const int b  = blockIdx.z;
    const int i0 = blockIdx.y * 128;
    const int n0 = blockIdx.x * 128;
    const bf16* __restrict__ Ahb = g_Ah + ((size_t)b << 20);
    const bf16* __restrict__ Alb = g_Al + ((size_t)b << 20);

    const int tid  = threadIdx.x;
    const int w    = tid >> 5;
    const int lane = tid & 31;
    const int wm   = w >> 2;
    const int wn   = w & 3;
    const int gid  = lane >> 2;
    const int tig  = lane & 3;

    const int crow = tid >> 1;
    const int cc8  = (tid & 1) * 8;
    const int cso  = crow * PA + cc8;
    uint32_t sAh0 = smem_u32(&sAh[0][cso]);
    uint32_t sAh1 = smem_u32(&sAh[1][cso]);
    uint32_t sAl0 = smem_u32(&sAl[0][cso]);
    uint32_t sAl1 = smem_u32(&sAl[1][cso]);
    uint32_t sBh0 = smem_u32(&sBh[0][cso]);
    uint32_t sBh1 = smem_u32(&sBh[1][cso]);
    uint32_t sBl0 = smem_u32(&sBl[0][cso]);
    uint32_t sBl1 = smem_u32(&sBl[1][cso]);
    const size_t gA = (size_t)(i0 + crow) * Dn + cc8;
    const size_t gB = (size_t)(n0 + crow) * Dn + cc8;

    const uint32_t aOff = (uint32_t)((wm * 64 + (lane & 15)) * PAB + (lane >> 4) * 16);
    const uint32_t bOff = (uint32_t)((wn * 32 + (lane & 7) + ((lane >> 4) << 3)) * PAB
                                     + ((lane >> 3) & 1) * 16);
    uint32_t aH0 = smem_u32(&sAh[0][0]) + aOff, aH1 = smem_u32(&sAh[1][0]) + aOff;
    uint32_t aL0 = smem_u32(&sAl[0][0]) + aOff, aL1 = smem_u32(&sAl[1][0]) + aOff;
    uint32_t bH0 = smem_u32(&sBh[0][0]) + bOff, bH1 = smem_u32(&sBh[1][0]) + bOff;
    uint32_t bL0 = smem_u32(&sBl[0][0]) + bOff, bL1 = smem_u32(&sBl[1][0]) + bOff;

    float acc[MT][NT][4];
    #pragma unroll
    for (int mt = 0; mt < MT; ++mt)
        #pragma unroll
        for (int nt = 0; nt < NT; ++nt)
            #pragma unroll
            for (int q = 0; q < 4; ++q) acc[mt][nt][q] = 0.f;

    cp_async16(sAh0, Ahb + gA);
    cp_async16(sAl0, Alb + gA);
    cp_async16(sBh0, g_GTh + gB);
    cp_async16(sBl0, g_GTl + gB);
    cp_commit();

    for (int kt = 0; kt < NK; ++kt) {
        int st = kt & 1;
        if (kt + 1 < NK) {
            int ko = (kt + 1) * BK;
            if (st == 0) {
                cp_async16(sAh1, Ahb + gA + ko);
                cp_async16(sAl1, Alb + gA + ko);
                cp_async16(sBh1, g_GTh + gB + ko);
                cp_async16(sBl1, g_GTl + gB + ko);
            } else {
                cp_async16(sAh0, Ahb + gA + ko);
                cp_async16(sAl0, Alb + gA + ko);
                cp_async16(sBh0, g_GTh + gB + ko);
                cp_async16(sBl0, g_GTl + gB + ko);
            }
        }
        cp_commit();
        cp_wait1();
        __syncthreads();

        const uint32_t aH = st ? aH1 : aH0;
        const uint32_t aL = st ? aL1 : aL0;
        const uint32_t bH = st ? bH1 : bH0;
        const uint32_t bL = st ? bL1 : bL0;

        uint32_t bh[NT][2], bl[NT][2];
        #pragma unroll
        for (int j = 0; j < 2; ++j) {
            uint32_t r0, r1, r2, r3;
            ldsm_x4(r0, r1, r2, r3, bH + j * 16 * PAB);
            bh[2 * j][0] = r0; bh[2 * j][1] = r1;
            bh[2 * j + 1][0] = r2; bh[2 * j + 1][1] = r3;
            ldsm_x4(r0, r1, r2, r3, bL + j * 16 * PAB);
            bl[2 * j][0] = r0; bl[2 * j][1] = r1;
            bl[2 * j + 1][0] = r2; bl[2 * j + 1][1] = r3;
        }
        #pragma unroll
        for (int mt = 0; mt < MT; ++mt) {
            uint32_t ah[4], al[4];
            ldsm_x4(ah[0], ah[1], ah[2], ah[3], aH + mt * 16 * PAB);
            ldsm_x4(al[0], al[1], al[2], al[3], aL + mt * 16 * PAB);
            #pragma unroll
            for (int nt = 0; nt < NT; ++nt) {
                mma_bf16(acc[mt][nt], ah, bh[nt]);
                mma_bf16(acc[mt][nt], ah, bl[nt]);
                mma_bf16(acc[mt][nt], al, bh[nt]);
            }
        }
        __syncthreads();
    }

    float* __restrict__ outb = out + (size_t)b * Dn * Dn;
    #pragma unroll
    for (int mt = 0; mt < MT; ++mt) {
        int row = i0 + wm * 64 + mt * 16 + gid;
        #pragma unroll
        for (int nt = 0; nt < NT; ++nt) {
            int col = n0 + wn * 32 + nt * 8 + tig * 2;
            float2 mbv = *reinterpret_cast<const float2*>(&g_mb[col]);
            float2 v0 = {acc[mt][nt][0] + mbv.x, acc[mt][nt][1] + mbv.y};
            float2 v1 = {acc[mt][nt][2] + mbv.x, acc[mt][nt][3] + mbv.y};
            *reinterpret_cast<float2*>(outb + (size_t)row * Dn + col) = v0;
            *reinterpret_cast<float2*>(outb + (size_t)(row + 8) * Dn + col) = v1;
        }
    }
}

// ---------------------------------------------------------------------------
// kernel_launch — dual-stream fork/join (created on first, uncaptured call;
// capture-legal event fork pattern). Falls back to single-stream order.
// ---------------------------------------------------------------------------
extern "C" void kernel_launch(void* const* d_in, const int* in_sizes, int n_in,
                              void* d_out, int out_size) {
    const float* x  = (const float*)d_in[0];
    const float* qw = (const float*)d_in[1];
    const float* ph = (const float*)d_in[2];
    const float* em = (const float*)d_in[3];
    const float* gw = (const float*)d_in[4];
    const float* gb = (const float*)d_in[5];
    float* out = (float*)d_out;

    static cudaStream_t s2 = nullptr;
    static cudaEvent_t eFork = nullptr, eM = nullptr, eJoin = nullptr;
    static bool init_tried = false;
    if (!init_tried) {
        init_tried = true;
        if (cudaStreamCreateWithFlags(&s2, cudaStreamNonBlocking) != cudaSuccess) s2 = nullptr;
        if (s2) {
            cudaEventCreateWithFlags(&eFork, cudaEventDisableTiming);
            cudaEventCreateWithFlags(&eM,    cudaEventDisableTiming);
            cudaEventCreateWithFlags(&eJoin, cudaEventDisableTiming);
        }
    }

    if (s2) {
        // fork
        cudaEventRecord(eFork, 0);
        cudaStreamWaitEvent(s2, eFork, 0);
        // branch A (main stream): the 400MB HBM-bound reduction
        reduce_w_kernel<<<(Dn * Dn / 4) / 256, 256>>>(gw);
        // branch B (s2): small-kernel chain
        reduce_b_kernel<<<Dn / 256, 256, 0, s2>>>(gb);
        split_QW_kernel<<<(Dn * Dn / 4) / 256, 256, 0, s2>>>(qw);
        transpose_split_E_kernel<<<dim3(Dn / 32, Dn / 32), dim3(32, 8), 0, s2>>>(em);
        gemm_M_kernel<<<dim3(Dn / 128, Dn / 128), 256, 0, s2>>>();
        cudaEventRecord(eM, s2);
        split_A_kernel<<<dim3((Dn * Dn / 4) / 256, Bn), 256, 0, s2>>>(x, ph);
        cudaEventRecord(eJoin, s2);
        // join: GT needs Wsum (branch A) + M (eM)
        cudaStreamWaitEvent(0, eM, 0);
        gemm_GT_kernel<<<dim3(Dn / 128, Dn / 128), 256>>>();
        cudaStreamWaitEvent(0, eJoin, 0);
        gemm_final_kernel<<<dim3(Dn / 128, Dn / 128, Bn), 256>>>(out);
    } else {
        // fallback: single-stream, dependency-correct order
        reduce_b_kernel<<<Dn / 256, 256>>>(gb);
        split_QW_kernel<<<(Dn * Dn / 4) / 256, 256>>>(qw);
        transpose_split_E_kernel<<<dim3(Dn / 32, Dn / 32), dim3(32, 8)>>>(em);
        gemm_M_kernel<<<dim3(Dn / 128, Dn / 128), 256>>>();
        split_A_kernel<<<dim3((Dn * Dn / 4) / 256, Bn), 256>>>(x, ph);
        reduce_w_kernel<<<(Dn * Dn / 4) / 256, 256>>>(gw);
        gemm_GT_kernel<<<dim3(Dn / 128, Dn / 128), 256>>>();
        gemm_final_kernel<<<dim3(Dn / 128, Dn / 128, Bn), 256>>>(out);
    }
}